// round 1
// baseline (speedup 1.0000x reference)
#include <cuda_runtime.h>
#include <math.h>

#define BB 2
#define LL 1000
#define DD 288
#define HH 8
#define DIMH 36
#define DFF_ 576
#define KS_ 250
#define NQ_ 250
#define BHN 16   // BB*HH

// ---------------- scratch (device globals; no allocs allowed) ----------------
__device__ float g_q[BHN*LL*DIMH];
__device__ float g_k[BHN*LL*DIMH];
__device__ float g_v[BHN*LL*DIMH];
__device__ float g_S[(size_t)BHN*LL*LL];      // 64 MB
__device__ float g_meas[BHN*LL];
__device__ int   g_idxq[BHN*NQ_];
__device__ float g_P[(size_t)BHN*NQ_*LL];     // 16 MB
__device__ float g_osel[BHN*NQ_*DIMH];
__device__ float g_vmean[BHN*DIMH];
__device__ float g_attn[BB*LL*DD];
__device__ float g_h1[BB*LL*DD];
__device__ float g_f1[BB*LL*DFF_];
__device__ float g_f2[BB*LL*DD];

// ---------------- reduction helpers ----------------
__device__ __forceinline__ float warpRedSum(float v){
#pragma unroll
  for (int o=16;o;o>>=1) v += __shfl_xor_sync(0xffffffffu, v, o);
  return v;
}
__device__ __forceinline__ float warpRedMax(float v){
#pragma unroll
  for (int o=16;o;o>>=1) v = fmaxf(v, __shfl_xor_sync(0xffffffffu, v, o));
  return v;
}
__device__ float blockRedSum(float v, float* sm, int nwarp){
  int w = threadIdx.x >> 5, lane = threadIdx.x & 31;
  v = warpRedSum(v);
  if (lane == 0) sm[w] = v;
  __syncthreads();
  float r;
  if (w == 0){
    r = (lane < nwarp) ? sm[lane] : 0.f;
    r = warpRedSum(r);
    if (lane == 0) sm[0] = r;
  }
  __syncthreads();
  r = sm[0];
  __syncthreads();
  return r;
}
__device__ float blockRedMax(float v, float* sm, int nwarp){
  int w = threadIdx.x >> 5, lane = threadIdx.x & 31;
  v = warpRedMax(v);
  if (lane == 0) sm[w] = v;
  __syncthreads();
  float r;
  if (w == 0){
    r = (lane < nwarp) ? sm[lane] : -INFINITY;
    r = warpRedMax(r);
    if (lane == 0) sm[0] = r;
  }
  __syncthreads();
  r = sm[0];
  __syncthreads();
  return r;
}

// ---------------- generic GEMM: C = act(A[M,K] @ W[N,K]^T + bias) ----------------
// MODE 0: plain [M,N] store.  MODE 1: scatter into [b,h,l,dim] q/k/v layout.
template<int MODE, int GELU>
__global__ void gemm_k(const float* __restrict__ A, const float* __restrict__ W,
                       const float* __restrict__ bias, float* __restrict__ C,
                       int M, int N, int K){
  __shared__ float As[64][16];
  __shared__ float Bs[16][65];
  int tid = threadIdx.x;
  int m0 = blockIdx.y * 64, n0 = blockIdx.x * 64;
  int tx = tid & 15, ty = tid >> 4;
  float acc[4][4] = {};
  for (int k0 = 0; k0 < K; k0 += 16){
    for (int i = tid; i < 1024; i += 256){
      int m = i >> 4, kk = i & 15;
      int gm = m0 + m;
      As[m][kk] = (gm < M) ? A[(size_t)gm*K + k0 + kk] : 0.f;
    }
    for (int i = tid; i < 1024; i += 256){
      int n = i >> 4, kk = i & 15;
      int gn = n0 + n;
      Bs[kk][n] = (gn < N) ? W[(size_t)gn*K + k0 + kk] : 0.f;
    }
    __syncthreads();
#pragma unroll
    for (int kk = 0; kk < 16; kk++){
      float a[4], b[4];
#pragma unroll
      for (int i = 0; i < 4; i++) a[i] = As[ty*4+i][kk];
#pragma unroll
      for (int j = 0; j < 4; j++) b[j] = Bs[kk][tx*4+j];
#pragma unroll
      for (int i = 0; i < 4; i++)
#pragma unroll
        for (int j = 0; j < 4; j++) acc[i][j] += a[i]*b[j];
    }
    __syncthreads();
  }
#pragma unroll
  for (int i = 0; i < 4; i++){
    int m = m0 + ty*4 + i;
    if (m >= M) continue;
#pragma unroll
    for (int j = 0; j < 4; j++){
      int n = n0 + tx*4 + j;
      if (n >= N) continue;
      float vv = acc[i][j] + bias[n];
      if (GELU) vv = 0.5f*vv*(1.0f + erff(vv*0.70710678118654752f));
      if (MODE == 0){
        C[(size_t)m*N + n] = vv;
      } else {
        int b_ = m / LL, l = m % LL;
        int h = n / DIMH, d = n % DIMH;
        C[(((size_t)b_*HH + h)*LL + l)*DIMH + d] = vv;
      }
    }
  }
}

// ---------------- S = Q K^T per (b,h): [1000,1000] ----------------
__global__ void sgemm_k(){
  __shared__ float Qs[64][37];
  __shared__ float Ks[64][37];
  int bh = blockIdx.z;
  int q0 = blockIdx.y*64, k0 = blockIdx.x*64;
  const float* Q  = g_q + (size_t)bh*LL*DIMH;
  const float* Kp = g_k + (size_t)bh*LL*DIMH;
  int tid = threadIdx.x;
  for (int i = tid; i < 64*DIMH; i += 256){
    int r = i / DIMH, d = i % DIMH;
    Qs[r][d] = (q0 + r < LL) ? Q[(q0+r)*DIMH + d] : 0.f;
    Ks[r][d] = (k0 + r < LL) ? Kp[(k0+r)*DIMH + d] : 0.f;
  }
  __syncthreads();
  int tx = tid & 15, ty = tid >> 4;
  float acc[4][4] = {};
#pragma unroll 4
  for (int d = 0; d < DIMH; d++){
    float a[4], b[4];
#pragma unroll
    for (int i = 0; i < 4; i++) a[i] = Qs[ty*4+i][d];
#pragma unroll
    for (int j = 0; j < 4; j++) b[j] = Ks[tx*4+j][d];
#pragma unroll
    for (int i = 0; i < 4; i++)
#pragma unroll
      for (int j = 0; j < 4; j++) acc[i][j] += a[i]*b[j];
  }
  float* Sp = g_S + (size_t)bh*LL*LL;
#pragma unroll
  for (int i = 0; i < 4; i++){
    int m = q0 + ty*4 + i;
    if (m >= LL) continue;
#pragma unroll
    for (int j = 0; j < 4; j++){
      int n = k0 + tx*4 + j;
      if (n >= LL) continue;
      Sp[(size_t)m*LL + n] = acc[i][j];
    }
  }
}

// ---------------- measure[l] = max_j S[l,idx[l,j]] - sum_j S[l,idx[l,j]] / L ----------------
__global__ void measure_k(const int* __restrict__ ik){
  __shared__ float sm[32];
  int l = blockIdx.x, bh = blockIdx.y, t = threadIdx.x;
  const float* Srow = g_S + ((size_t)bh*LL + l)*LL;
  float mx = -INFINITY, s = 0.f;
  if (t < KS_){
    int id = ik[l*KS_ + t];
    float vv = Srow[id];
    mx = vv; s = vv;
  }
  mx = blockRedMax(mx, sm, 8);
  s  = blockRedSum(s, sm, 8);
  if (t == 0) g_meas[bh*LL + l] = mx - s * (1.0f/(float)LL);
}

// ---------------- top-NQ per (b,h): bitonic sort 1024 ----------------
__global__ void topk_k(){
  __shared__ float key[1024];
  __shared__ int   kid[1024];
  int bh = blockIdx.x, tid = threadIdx.x;
  for (int i = tid; i < 1024; i += 256){
    key[i] = (i < LL) ? -g_meas[bh*LL + i] : INFINITY;  // ascending of -measure
    kid[i] = i;
  }
  __syncthreads();
  for (int k = 2; k <= 1024; k <<= 1){
    for (int j = k >> 1; j > 0; j >>= 1){
      for (int i = tid; i < 1024; i += 256){
        int ixj = i ^ j;
        if (ixj > i){
          bool up = ((i & k) == 0);
          float a = key[i], b = key[ixj];
          int ia = kid[i], ib = kid[ixj];
          bool gt = (a > b) || (a == b && ia > ib);
          if (gt == up){
            key[i] = b; key[ixj] = a;
            kid[i] = ib; kid[ixj] = ia;
          }
        }
      }
      __syncthreads();
    }
  }
  for (int i = tid; i < NQ_; i += 256) g_idxq[bh*NQ_ + i] = kid[i];
}

// ---------------- softmax rows of selected queries (scale 1/6) -> P ----------------
__global__ void softmax_k(){
  __shared__ float sm[32];
  int qi = blockIdx.x, bh = blockIdx.y, t = threadIdx.x;
  int lq = g_idxq[bh*NQ_ + qi];
  const float* row = g_S + ((size_t)bh*LL + lq)*LL;
  float* prow = g_P + ((size_t)bh*NQ_ + qi)*LL;
  const float sc = 1.0f/6.0f;   // 1/sqrt(36)
  float mx = -INFINITY;
  for (int i = t; i < LL; i += 256) mx = fmaxf(mx, row[i]*sc);
  mx = blockRedMax(mx, sm, 8);
  float s = 0.f;
  for (int i = t; i < LL; i += 256){
    float e = expf(row[i]*sc - mx);
    prow[i] = e; s += e;
  }
  s = blockRedSum(s, sm, 8);
  float inv = 1.0f/s;
  for (int i = t; i < LL; i += 256) prow[i] *= inv;
}

// ---------------- out_sel = P[250,1000] @ V[1000,36] per bh ----------------
__global__ void pv_k(){
  __shared__ float Ps[64][65];
  __shared__ float Vs[64][37];
  int bh = blockIdx.y, q0 = blockIdx.x*64;
  int tid = threadIdx.x;
  int r = tid >> 2, cg = tid & 3;   // 64 rows x 4 col-groups of 9
  float acc[9] = {};
  const float* Vp = g_v + (size_t)bh*LL*DIMH;
  const float* Pp = g_P + (size_t)bh*NQ_*LL;
  for (int kk0 = 0; kk0 < LL; kk0 += 64){
    for (int i = tid; i < 64*64; i += 256){
      int rr = i >> 6, kk = i & 63;
      Ps[rr][kk] = (q0+rr < NQ_ && kk0+kk < LL) ? Pp[(size_t)(q0+rr)*LL + kk0+kk] : 0.f;
    }
    for (int i = tid; i < 64*DIMH; i += 256){
      int rr = i / DIMH, d = i % DIMH;
      Vs[rr][d] = (kk0+rr < LL) ? Vp[(kk0+rr)*DIMH + d] : 0.f;
    }
    __syncthreads();
#pragma unroll 4
    for (int kk = 0; kk < 64; kk++){
      float p = Ps[r][kk];
#pragma unroll
      for (int c = 0; c < 9; c++) acc[c] += p * Vs[kk][cg*9 + c];
    }
    __syncthreads();
  }
  if (q0 + r < NQ_){
#pragma unroll
    for (int c = 0; c < 9; c++)
      g_osel[((size_t)bh*NQ_ + q0 + r)*DIMH + cg*9 + c] = acc[c];
  }
}

// ---------------- vmean ----------------
__global__ void vmean_k(){
  __shared__ float sm[32];
  int d = blockIdx.x, bh = blockIdx.y, t = threadIdx.x;
  float s = 0.f;
  for (int l = t; l < LL; l += 256) s += g_v[((size_t)bh*LL + l)*DIMH + d];
  s = blockRedSum(s, sm, 8);
  if (t == 0) g_vmean[bh*DIMH + d] = s * (1.0f/(float)LL);
}

// ---------------- fill attn with broadcast vmean ----------------
__global__ void fill_k(){
  int idx = blockIdx.x*256 + threadIdx.x;
  if (idx >= BB*LL*DD) return;
  int c = idx % DD;
  int bl = idx / DD;
  int b_ = bl / LL;
  int h = c / DIMH, d = c % DIMH;
  g_attn[idx] = g_vmean[(b_*HH + h)*DIMH + d];
}

// ---------------- scatter active-query outputs ----------------
__global__ void scatter_k(){
  int qi = blockIdx.x, bh = blockIdx.y, t = threadIdx.x;
  if (t >= DIMH) return;
  int lstar = g_idxq[bh*NQ_ + qi];
  int b_ = bh / HH, h = bh % HH;
  g_attn[((size_t)b_*LL + lstar)*DD + h*DIMH + t] =
      g_osel[((size_t)bh*NQ_ + qi)*DIMH + t];
}

// ---------------- LayerNorm(A + B) ----------------
__global__ void ln_kernel(const float* __restrict__ A, const float* __restrict__ Bv,
                          const float* __restrict__ gamma, const float* __restrict__ beta,
                          float* __restrict__ out){
  __shared__ float sm[32];
  int row = blockIdx.x, t = threadIdx.x;  // 288 threads = 9 warps
  float s = A[(size_t)row*DD + t] + Bv[(size_t)row*DD + t];
  float mu = blockRedSum(s, sm, 9) * (1.0f/(float)DD);
  float d = s - mu;
  float var = blockRedSum(d*d, sm, 9) * (1.0f/(float)DD);
  out[(size_t)row*DD + t] = d * rsqrtf(var + 1e-5f) * gamma[t] + beta[t];
}

// ---------------- launch ----------------
extern "C" void kernel_launch(void* const* d_in, const int* in_sizes, int n_in,
                              void* d_out, int out_size){
  const float* x  = (const float*)d_in[0];
  const int*   ik = (const int*)  d_in[1];
  const float* Wq = (const float*)d_in[2];  const float* bq = (const float*)d_in[3];
  const float* Wk = (const float*)d_in[4];  const float* bk = (const float*)d_in[5];
  const float* Wv = (const float*)d_in[6];  const float* bv = (const float*)d_in[7];
  const float* W1 = (const float*)d_in[8];  const float* b1 = (const float*)d_in[9];
  const float* W2 = (const float*)d_in[10]; const float* b2 = (const float*)d_in[11];
  const float* g1 = (const float*)d_in[12]; const float* be1 = (const float*)d_in[13];
  const float* g2 = (const float*)d_in[14]; const float* be2 = (const float*)d_in[15];
  float* out = (float*)d_out;

  float *pq, *pk, *pv, *ph1, *pf1, *pf2, *pattn;
  cudaGetSymbolAddress((void**)&pq,   g_q);
  cudaGetSymbolAddress((void**)&pk,   g_k);
  cudaGetSymbolAddress((void**)&pv,   g_v);
  cudaGetSymbolAddress((void**)&ph1,  g_h1);
  cudaGetSymbolAddress((void**)&pf1,  g_f1);
  cudaGetSymbolAddress((void**)&pf2,  g_f2);
  cudaGetSymbolAddress((void**)&pattn, g_attn);

  const int M = BB*LL;  // 2000
  dim3 gqkv((DD + 63)/64, (M + 63)/64);
  gemm_k<1,0><<<gqkv, 256>>>(x, Wq, bq, pq, M, DD, DD);
  gemm_k<1,0><<<gqkv, 256>>>(x, Wk, bk, pk, M, DD, DD);
  gemm_k<1,0><<<gqkv, 256>>>(x, Wv, bv, pv, M, DD, DD);

  sgemm_k<<<dim3(16,16,BHN), 256>>>();
  measure_k<<<dim3(LL, BHN), 256>>>(ik);
  topk_k<<<BHN, 256>>>();
  softmax_k<<<dim3(NQ_, BHN), 256>>>();
  pv_k<<<dim3(4, BHN), 256>>>();
  vmean_k<<<dim3(DIMH, BHN), 256>>>();
  fill_k<<<(BB*LL*DD + 255)/256, 256>>>();
  scatter_k<<<dim3(NQ_, BHN), 64>>>();

  ln_kernel<<<M, DD>>>(x, pattn, g1, be1, ph1);

  gemm_k<0,1><<<dim3((DFF_ + 63)/64, (M + 63)/64), 256>>>(ph1, W1, b1, pf1, M, DFF_, DD);
  gemm_k<0,1><<<dim3((DD   + 63)/64, (M + 63)/64), 256>>>(pf1, W2, b2, pf2, M, DD, DFF_);

  ln_kernel<<<M, DD>>>(pf2, ph1, g2, be2, out);
}

// round 2
// speedup vs baseline: 1.6204x; 1.6204x over previous
#include <cuda_runtime.h>
#include <math.h>

#define BB 2
#define LL 1000
#define DD 288
#define HH 8
#define DIMH 36
#define DFF_ 576
#define KS_ 250
#define NQ_ 250
#define BHN 16   // BB*HH
#define KSPLIT 4

// ---------------- scratch (device globals; no allocs allowed) ----------------
__device__ __align__(16) float g_q[BHN*LL*DIMH];
__device__ __align__(16) float g_k[BHN*LL*DIMH];
__device__ __align__(16) float g_v[BHN*LL*DIMH];
__device__ __align__(16) float g_S[(size_t)BHN*LL*LL];      // 64 MB
__device__ float g_meas[BHN*LL];
__device__ int   g_idxq[BHN*NQ_];
__device__ float g_m[BHN*NQ_];
__device__ float g_inv[BHN*NQ_];
__device__ float g_opart[(size_t)KSPLIT*BHN*NQ_*DIMH];
__device__ float g_vmean[BHN*DIMH];
__device__ __align__(16) float g_attn[BB*LL*DD];
__device__ __align__(16) float g_h1[BB*LL*DD];
__device__ __align__(16) float g_f1[BB*LL*DFF_];
__device__ __align__(16) float g_f2[BB*LL*DD];

// ---------------- reduction helpers ----------------
__device__ __forceinline__ float warpRedSum(float v){
#pragma unroll
  for (int o=16;o;o>>=1) v += __shfl_xor_sync(0xffffffffu, v, o);
  return v;
}
__device__ __forceinline__ float warpRedMax(float v){
#pragma unroll
  for (int o=16;o;o>>=1) v = fmaxf(v, __shfl_xor_sync(0xffffffffu, v, o));
  return v;
}
__device__ float blockRedSum(float v, float* sm, int nwarp){
  int w = threadIdx.x >> 5, lane = threadIdx.x & 31;
  v = warpRedSum(v);
  if (lane == 0) sm[w] = v;
  __syncthreads();
  float r;
  if (w == 0){
    r = (lane < nwarp) ? sm[lane] : 0.f;
    r = warpRedSum(r);
    if (lane == 0) sm[0] = r;
  }
  __syncthreads();
  r = sm[0];
  __syncthreads();
  return r;
}
__device__ float blockRedMax(float v, float* sm, int nwarp){
  int w = threadIdx.x >> 5, lane = threadIdx.x & 31;
  v = warpRedMax(v);
  if (lane == 0) sm[w] = v;
  __syncthreads();
  float r;
  if (w == 0){
    r = (lane < nwarp) ? sm[lane] : -INFINITY;
    r = warpRedMax(r);
    if (lane == 0) sm[0] = r;
  }
  __syncthreads();
  r = sm[0];
  __syncthreads();
  return r;
}

// ---------------- GEMM 96x96 tiles, 6x6 microtile: C = act(A[M,K] @ W[N,K]^T + b) ----------------
// MODE 0: plain [M,N] store.  MODE 1: scatter into [b,h,l,dim] q/k/v layout.
// Requires K % 32 == 0.
template<int MODE, int GELU>
__global__ void __launch_bounds__(256) gemm96(const float* __restrict__ A, const float* __restrict__ W,
                                              const float* __restrict__ bias, float* __restrict__ C,
                                              int M, int N, int K){
  __shared__ __align__(16) float As[96][36];   // [m][kk], 32 used cols, pad 36
  __shared__ float Bs[32][97];                 // [kk][n]
  int tid = threadIdx.x;
  int m0 = blockIdx.y * 96, n0 = blockIdx.x * 96;
  int tx = tid & 15, ty = tid >> 4;
  float acc[6][6] = {};
  for (int k0 = 0; k0 < K; k0 += 32){
#pragma unroll
    for (int it = 0; it < 3; it++){
      int i = tid + it*256;           // 768 float4 = 96 rows x 8
      int m = i >> 3, kv = i & 7;
      int gm = m0 + m;
      float4 v = (gm < M) ? *(const float4*)(A + (size_t)gm*K + k0 + 4*kv)
                          : make_float4(0.f,0.f,0.f,0.f);
      *(float4*)(&As[m][4*kv]) = v;
    }
#pragma unroll
    for (int it = 0; it < 3; it++){
      int i = tid + it*256;
      int n = i >> 3, kv = i & 7;
      int gn = n0 + n;
      float4 v = (gn < N) ? *(const float4*)(W + (size_t)gn*K + k0 + 4*kv)
                          : make_float4(0.f,0.f,0.f,0.f);
      Bs[4*kv+0][n] = v.x; Bs[4*kv+1][n] = v.y;
      Bs[4*kv+2][n] = v.z; Bs[4*kv+3][n] = v.w;
    }
    __syncthreads();
#pragma unroll 8
    for (int kk = 0; kk < 32; kk++){
      float a[6], b[6];
#pragma unroll
      for (int i = 0; i < 6; i++) a[i] = As[ty*6+i][kk];
#pragma unroll
      for (int j = 0; j < 6; j++) b[j] = Bs[kk][tx*6+j];
#pragma unroll
      for (int i = 0; i < 6; i++)
#pragma unroll
        for (int j = 0; j < 6; j++) acc[i][j] += a[i]*b[j];
    }
    __syncthreads();
  }
#pragma unroll
  for (int i = 0; i < 6; i++){
    int m = m0 + ty*6 + i;
    if (m >= M) continue;
#pragma unroll
    for (int j = 0; j < 6; j++){
      int n = n0 + tx*6 + j;
      if (n >= N) continue;
      float vv = acc[i][j] + bias[n];
      if (GELU) vv = 0.5f*vv*(1.0f + erff(vv*0.70710678118654752f));
      if (MODE == 0){
        C[(size_t)m*N + n] = vv;
      } else {
        int b_ = m / LL, l = m % LL;
        int h = n / DIMH, d = n % DIMH;
        C[(((size_t)b_*HH + h)*LL + l)*DIMH + d] = vv;
      }
    }
  }
}

// ---------------- S = Q K^T per (b,h), 96x96 tiles, 6x6 microtile ----------------
__global__ void __launch_bounds__(256) sgemm96(){
  __shared__ float Qs[96][37];
  __shared__ float Ks[96][37];
  int bh = blockIdx.z;
  int q0 = blockIdx.y*96, k0 = blockIdx.x*96;
  const float* Q  = g_q + (size_t)bh*LL*DIMH;
  const float* Kp = g_k + (size_t)bh*LL*DIMH;
  int tid = threadIdx.x;
#pragma unroll
  for (int it = 0; it < 4; it++){
    int i = tid + it*256;             // 864 float4 = 96 rows x 9
    if (i < 864){
      int r = i / 9, dv = i % 9;
      int gq = q0 + r, gk = k0 + r;
      float4 vq = (gq < LL) ? *(const float4*)(Q  + (size_t)gq*DIMH + 4*dv)
                            : make_float4(0.f,0.f,0.f,0.f);
      float4 vk = (gk < LL) ? *(const float4*)(Kp + (size_t)gk*DIMH + 4*dv)
                            : make_float4(0.f,0.f,0.f,0.f);
      Qs[r][4*dv+0]=vq.x; Qs[r][4*dv+1]=vq.y; Qs[r][4*dv+2]=vq.z; Qs[r][4*dv+3]=vq.w;
      Ks[r][4*dv+0]=vk.x; Ks[r][4*dv+1]=vk.y; Ks[r][4*dv+2]=vk.z; Ks[r][4*dv+3]=vk.w;
    }
  }
  __syncthreads();
  int tx = tid & 15, ty = tid >> 4;
  float acc[6][6] = {};
#pragma unroll 6
  for (int d = 0; d < DIMH; d++){
    float a[6], b[6];
#pragma unroll
    for (int i = 0; i < 6; i++) a[i] = Qs[ty*6+i][d];
#pragma unroll
    for (int j = 0; j < 6; j++) b[j] = Ks[tx*6+j][d];
#pragma unroll
    for (int i = 0; i < 6; i++)
#pragma unroll
      for (int j = 0; j < 6; j++) acc[i][j] += a[i]*b[j];
  }
  float* Sp = g_S + (size_t)bh*LL*LL;
#pragma unroll
  for (int i = 0; i < 6; i++){
    int m = q0 + ty*6 + i;
    if (m >= LL) continue;
#pragma unroll
    for (int j = 0; j < 6; j++){
      int n = k0 + tx*6 + j;
      if (n >= LL) continue;
      Sp[(size_t)m*LL + n] = acc[i][j];
    }
  }
}

// ---------------- measure[l] = max_j S[l,idx[l,j]] - sum_j S[l,idx[l,j]] / L ----------------
__global__ void measure_k(const int* __restrict__ ik){
  __shared__ float sm[32];
  int l = blockIdx.x, bh = blockIdx.y, t = threadIdx.x;
  const float* Srow = g_S + ((size_t)bh*LL + l)*LL;
  float mx = -INFINITY, s = 0.f;
  if (t < KS_){
    int id = ik[l*KS_ + t];
    float vv = Srow[id];
    mx = vv; s = vv;
  }
  mx = blockRedMax(mx, sm, 8);
  s  = blockRedSum(s, sm, 8);
  if (t == 0) g_meas[bh*LL + l] = mx - s * (1.0f/(float)LL);
}

// ---------------- top-NQ per (b,h): bitonic sort 1024, 512 threads ----------------
__global__ void topk_k(){
  __shared__ float key[1024];
  __shared__ int   kid[1024];
  int bh = blockIdx.x, tid = threadIdx.x;
  for (int i = tid; i < 1024; i += 512){
    key[i] = (i < LL) ? -g_meas[bh*LL + i] : INFINITY;  // ascending of -measure
    kid[i] = i;
  }
  __syncthreads();
  for (int k = 2; k <= 1024; k <<= 1){
    for (int j = k >> 1; j > 0; j >>= 1){
      for (int i = tid; i < 1024; i += 512){
        int ixj = i ^ j;
        if (ixj > i){
          bool up = ((i & k) == 0);
          float a = key[i], b = key[ixj];
          int ia = kid[i], ib = kid[ixj];
          bool gt = (a > b) || (a == b && ia > ib);
          if (gt == up){
            key[i] = b; key[ixj] = a;
            kid[i] = ib; kid[ixj] = ia;
          }
        }
      }
      __syncthreads();
    }
  }
  for (int i = tid; i < NQ_; i += 512) g_idxq[bh*NQ_ + i] = kid[i];
}

// ---------------- per-selected-query softmax stats: m = max*sc, inv = 1/sum(exp) ----------------
__global__ void msum_k(){
  int tid = threadIdx.x;
  int w = tid >> 5, lane = tid & 31;
  int q = blockIdx.x*8 + w;
  int bh = blockIdx.y;
  if (q >= NQ_) return;
  const float sc = 1.0f/6.0f;
  int lq = g_idxq[bh*NQ_ + q];
  const float* row = g_S + ((size_t)bh*LL + lq)*LL;
  float mx = -INFINITY;
  for (int i = lane; i < LL; i += 32) mx = fmaxf(mx, row[i]);
  mx = warpRedMax(mx);
  float m = mx * sc;
  float s = 0.f;
  for (int i = lane; i < LL; i += 32) s += __expf(row[i]*sc - m);
  s = warpRedSum(s);
  if (lane == 0){ g_m[bh*NQ_ + q] = m; g_inv[bh*NQ_ + q] = 1.0f/s; }
}

// ---------------- fused softmax+PV, k-split partials ----------------
__global__ void __launch_bounds__(256) spv_k(){
  __shared__ float Ps[64][65];
  __shared__ float Vs[64][37];
  __shared__ float mS[64], invS[64];
  __shared__ int   lqS[64];
  int tid = threadIdx.x;
  int q0 = blockIdx.x*64;
  int ksb = blockIdx.y;
  int bh = blockIdx.z;
  int kstart = ksb*(LL/KSPLIT), kend = kstart + (LL/KSPLIT);
  const float sc = 1.0f/6.0f;
  if (tid < 64){
    int gq = q0 + tid;
    if (gq < NQ_){
      lqS[tid] = g_idxq[bh*NQ_ + gq];
      mS[tid]  = g_m[bh*NQ_ + gq];
      invS[tid]= g_inv[bh*NQ_ + gq];
    } else { lqS[tid]=0; mS[tid]=0.f; invS[tid]=0.f; }
  }
  __syncthreads();
  const float* Vp = g_v + (size_t)bh*LL*DIMH;
  const float* Sbh = g_S + (size_t)bh*LL*LL;
  int r = tid >> 2, cg = tid & 3;
  float acc[9] = {};
  for (int k0 = kstart; k0 < kend; k0 += 64){
    for (int i = tid; i < 64*DIMH; i += 256){
      int rr = i / DIMH, d = i % DIMH;
      int kr = k0 + rr;
      Vs[rr][d] = (kr < kend) ? Vp[(size_t)kr*DIMH + d] : 0.f;
    }
    for (int i = tid; i < 4096; i += 256){
      int qq = i >> 6, kk = i & 63;
      int kr = k0 + kk;
      float val = 0.f;
      if (q0 + qq < NQ_ && kr < kend)
        val = __expf(Sbh[(size_t)lqS[qq]*LL + kr]*sc - mS[qq]) * invS[qq];
      Ps[qq][kk] = val;
    }
    __syncthreads();
#pragma unroll 4
    for (int kk = 0; kk < 64; kk++){
      float p = Ps[r][kk];
#pragma unroll
      for (int c = 0; c < 9; c++) acc[c] += p * Vs[kk][cg*9 + c];
    }
    __syncthreads();
  }
  if (q0 + r < NQ_){
    float* dst = g_opart + (((size_t)ksb*BHN + bh)*NQ_ + q0 + r)*DIMH + cg*9;
#pragma unroll
    for (int c = 0; c < 9; c++) dst[c] = acc[c];
  }
}

// ---------------- vmean ----------------
__global__ void vmean_k(){
  __shared__ float sm[32];
  int d = blockIdx.x, bh = blockIdx.y, t = threadIdx.x;
  float s = 0.f;
  for (int l = t; l < LL; l += 256) s += g_v[((size_t)bh*LL + l)*DIMH + d];
  s = blockRedSum(s, sm, 8);
  if (t == 0) g_vmean[bh*DIMH + d] = s * (1.0f/(float)LL);
}

// ---------------- fill attn with broadcast vmean ----------------
__global__ void fill_k(){
  int idx = blockIdx.x*256 + threadIdx.x;
  if (idx >= BB*LL*DD) return;
  int c = idx % DD;
  int bl = idx / DD;
  int b_ = bl / LL;
  int h = c / DIMH, d = c % DIMH;
  g_attn[idx] = g_vmean[(b_*HH + h)*DIMH + d];
}

// ---------------- scatter active-query outputs (sums KSPLIT partials) ----------------
__global__ void scatter_k(){
  int qi = blockIdx.x, bh = blockIdx.y, t = threadIdx.x;
  if (t >= DIMH) return;
  int lstar = g_idxq[bh*NQ_ + qi];
  int b_ = bh / HH, h = bh % HH;
  float s = 0.f;
#pragma unroll
  for (int ks = 0; ks < KSPLIT; ks++)
    s += g_opart[(((size_t)ks*BHN + bh)*NQ_ + qi)*DIMH + t];
  g_attn[((size_t)b_*LL + lstar)*DD + h*DIMH + t] = s;
}

// ---------------- LayerNorm(A + B) ----------------
__global__ void ln_kernel(const float* __restrict__ A, const float* __restrict__ Bv,
                          const float* __restrict__ gamma, const float* __restrict__ beta,
                          float* __restrict__ out){
  __shared__ float sm[32];
  int row = blockIdx.x, t = threadIdx.x;  // 288 threads = 9 warps
  float s = A[(size_t)row*DD + t] + Bv[(size_t)row*DD + t];
  float mu = blockRedSum(s, sm, 9) * (1.0f/(float)DD);
  float d = s - mu;
  float var = blockRedSum(d*d, sm, 9) * (1.0f/(float)DD);
  out[(size_t)row*DD + t] = d * rsqrtf(var + 1e-5f) * gamma[t] + beta[t];
}

// ---------------- launch ----------------
extern "C" void kernel_launch(void* const* d_in, const int* in_sizes, int n_in,
                              void* d_out, int out_size){
  const float* x  = (const float*)d_in[0];
  const int*   ik = (const int*)  d_in[1];
  const float* Wq = (const float*)d_in[2];  const float* bq = (const float*)d_in[3];
  const float* Wk = (const float*)d_in[4];  const float* bk = (const float*)d_in[5];
  const float* Wv = (const float*)d_in[6];  const float* bv = (const float*)d_in[7];
  const float* W1 = (const float*)d_in[8];  const float* b1 = (const float*)d_in[9];
  const float* W2 = (const float*)d_in[10]; const float* b2 = (const float*)d_in[11];
  const float* g1 = (const float*)d_in[12]; const float* be1 = (const float*)d_in[13];
  const float* g2 = (const float*)d_in[14]; const float* be2 = (const float*)d_in[15];
  float* out = (float*)d_out;

  float *pq, *pk, *pv, *ph1, *pf1, *pf2, *pattn;
  cudaGetSymbolAddress((void**)&pq,   g_q);
  cudaGetSymbolAddress((void**)&pk,   g_k);
  cudaGetSymbolAddress((void**)&pv,   g_v);
  cudaGetSymbolAddress((void**)&ph1,  g_h1);
  cudaGetSymbolAddress((void**)&pf1,  g_f1);
  cudaGetSymbolAddress((void**)&pf2,  g_f2);
  cudaGetSymbolAddress((void**)&pattn, g_attn);

  const int M = BB*LL;  // 2000
  dim3 gqkv((DD + 95)/96, (M + 95)/96);       // 3 x 21
  gemm96<1,0><<<gqkv, 256>>>(x, Wq, bq, pq, M, DD, DD);
  gemm96<1,0><<<gqkv, 256>>>(x, Wk, bk, pk, M, DD, DD);
  gemm96<1,0><<<gqkv, 256>>>(x, Wv, bv, pv, M, DD, DD);

  sgemm96<<<dim3(11,11,BHN), 256>>>();
  measure_k<<<dim3(LL, BHN), 256>>>(ik);
  topk_k<<<BHN, 512>>>();
  msum_k<<<dim3((NQ_ + 7)/8, BHN), 256>>>();
  spv_k<<<dim3((NQ_ + 63)/64, KSPLIT, BHN), 256>>>();
  vmean_k<<<dim3(DIMH, BHN), 256>>>();
  fill_k<<<(BB*LL*DD + 255)/256, 256>>>();
  scatter_k<<<dim3(NQ_, BHN), 64>>>();

  ln_kernel<<<M, DD>>>(x, pattn, g1, be1, ph1);

  gemm96<0,1><<<dim3((DFF_ + 95)/96, (M + 95)/96), 256>>>(ph1, W1, b1, pf1, M, DFF_, DD);
  gemm96<0,1><<<dim3((DD   + 95)/96, (M + 95)/96), 256>>>(pf1, W2, b2, pf2, M, DD, DFF_);

  ln_kernel<<<M, DD>>>(pf2, ph1, g2, be2, out);
}

// round 3
// speedup vs baseline: 2.1679x; 1.3378x over previous
#include <cuda_runtime.h>
#include <math.h>

#define BB 2
#define LL 1000
#define DD 288
#define HH 8
#define DIMH 36
#define DFF_ 576
#define KS_ 250
#define NQ_ 250
#define BHN 16   // BB*HH
#define KSPLIT 4

// ---------------- scratch (device globals; no allocs allowed) ----------------
__device__ __align__(16) float g_q[BHN*LL*DIMH];
__device__ __align__(16) float g_k[BHN*LL*DIMH];
__device__ __align__(16) float g_v[BHN*LL*DIMH];
__device__ __align__(16) float g_S[(size_t)BHN*LL*LL];      // 64 MB
__device__ float g_meas[BHN*LL];
__device__ int   g_idxq[BHN*NQ_];
__device__ float g_m[BHN*NQ_];
__device__ float g_inv[BHN*NQ_];
__device__ float g_opart[(size_t)KSPLIT*BHN*NQ_*DIMH];
__device__ float g_vmean[BHN*DIMH];
__device__ __align__(16) float g_attn[BB*LL*DD];
__device__ __align__(16) float g_h1[BB*LL*DD];
__device__ __align__(16) float g_f1[BB*LL*DFF_];
__device__ __align__(16) float g_f2[BB*LL*DD];

// ---------------- reduction helpers ----------------
__device__ __forceinline__ float warpRedSum(float v){
#pragma unroll
  for (int o=16;o;o>>=1) v += __shfl_xor_sync(0xffffffffu, v, o);
  return v;
}
__device__ __forceinline__ float warpRedMax(float v){
#pragma unroll
  for (int o=16;o;o>>=1) v = fmaxf(v, __shfl_xor_sync(0xffffffffu, v, o));
  return v;
}
__device__ float blockRedSum(float v, float* sm, int nwarp){
  int w = threadIdx.x >> 5, lane = threadIdx.x & 31;
  v = warpRedSum(v);
  if (lane == 0) sm[w] = v;
  __syncthreads();
  float r;
  if (w == 0){
    r = (lane < nwarp) ? sm[lane] : 0.f;
    r = warpRedSum(r);
    if (lane == 0) sm[0] = r;
  }
  __syncthreads();
  r = sm[0];
  __syncthreads();
  return r;
}
__device__ float blockRedMax(float v, float* sm, int nwarp){
  int w = threadIdx.x >> 5, lane = threadIdx.x & 31;
  v = warpRedMax(v);
  if (lane == 0) sm[w] = v;
  __syncthreads();
  float r;
  if (w == 0){
    r = (lane < nwarp) ? sm[lane] : -INFINITY;
    r = warpRedMax(r);
    if (lane == 0) sm[0] = r;
  }
  __syncthreads();
  r = sm[0];
  __syncthreads();
  return r;
}

// ---------------- dense GEMM body: 96x96 tile, 6x6 micro, reg-staged prefetch ----------------
// C = act(A[M,K] @ W[N,K]^T + bias).  MODE 0: [M,N] store. MODE 1: scatter to q/k/v layout.
// K % 32 == 0.
template<int MODE, int GELU>
__device__ __forceinline__ void gemm_body(const float* __restrict__ A, const float* __restrict__ W,
                                          const float* __restrict__ bias, float* __restrict__ C,
                                          int M, int N, int K){
  __shared__ __align__(16) float As[96][36];   // [m][kk] (32 used, pad to 36 for f4 align)
  __shared__ float Bs[32][97];                 // [kk][n]
  int tid = threadIdx.x;
  int m0 = blockIdx.y * 96, n0 = blockIdx.x * 96;
  int tx = tid & 15, ty = tid >> 4;
  float acc[6][6] = {};
  float4 ra[3], rb[3];
  const float4 z4 = make_float4(0.f,0.f,0.f,0.f);

  // load chunk 0 into regs
#pragma unroll
  for (int it = 0; it < 3; it++){
    int i = tid + it*256;
    int m = i >> 3, kv = i & 7;
    int gm = m0 + m, gn = n0 + m;
    ra[it] = (gm < M) ? *(const float4*)(A + (size_t)gm*K + 4*kv) : z4;
    rb[it] = (gn < N) ? *(const float4*)(W + (size_t)gn*K + 4*kv) : z4;
  }
  // store chunk 0
#pragma unroll
  for (int it = 0; it < 3; it++){
    int i = tid + it*256;
    int m = i >> 3, kv = i & 7;
    *(float4*)(&As[m][4*kv]) = ra[it];
    Bs[4*kv+0][m] = rb[it].x; Bs[4*kv+1][m] = rb[it].y;
    Bs[4*kv+2][m] = rb[it].z; Bs[4*kv+3][m] = rb[it].w;
  }
  __syncthreads();

  for (int k0 = 0; k0 < K; k0 += 32){
    bool more = (k0 + 32) < K;
    if (more){
#pragma unroll
      for (int it = 0; it < 3; it++){
        int i = tid + it*256;
        int m = i >> 3, kv = i & 7;
        int gm = m0 + m, gn = n0 + m;
        ra[it] = (gm < M) ? *(const float4*)(A + (size_t)gm*K + k0 + 32 + 4*kv) : z4;
        rb[it] = (gn < N) ? *(const float4*)(W + (size_t)gn*K + k0 + 32 + 4*kv) : z4;
      }
    }
#pragma unroll 8
    for (int kk = 0; kk < 32; kk++){
      float a[6], b[6];
#pragma unroll
      for (int i = 0; i < 6; i++) a[i] = As[ty*6+i][kk];
#pragma unroll
      for (int j = 0; j < 6; j++) b[j] = Bs[kk][tx*6+j];
#pragma unroll
      for (int i = 0; i < 6; i++)
#pragma unroll
        for (int j = 0; j < 6; j++) acc[i][j] += a[i]*b[j];
    }
    __syncthreads();
    if (more){
#pragma unroll
      for (int it = 0; it < 3; it++){
        int i = tid + it*256;
        int m = i >> 3, kv = i & 7;
        *(float4*)(&As[m][4*kv]) = ra[it];
        Bs[4*kv+0][m] = rb[it].x; Bs[4*kv+1][m] = rb[it].y;
        Bs[4*kv+2][m] = rb[it].z; Bs[4*kv+3][m] = rb[it].w;
      }
      __syncthreads();
    }
  }
#pragma unroll
  for (int i = 0; i < 6; i++){
    int m = m0 + ty*6 + i;
    if (m >= M) continue;
#pragma unroll
    for (int j = 0; j < 6; j++){
      int n = n0 + tx*6 + j;
      if (n >= N) continue;
      float vv = acc[i][j] + bias[n];
      if (GELU) vv = 0.5f*vv*(1.0f + erff(vv*0.70710678118654752f));
      if (MODE == 0){
        C[(size_t)m*N + n] = vv;
      } else {
        int b_ = m / LL, l = m % LL;
        int h = n / DIMH, d = n % DIMH;
        C[(((size_t)b_*HH + h)*LL + l)*DIMH + d] = vv;
      }
    }
  }
}

__global__ void __launch_bounds__(256) qkv_k(const float* __restrict__ x,
    const float* __restrict__ Wq, const float* __restrict__ bq,
    const float* __restrict__ Wk, const float* __restrict__ bk,
    const float* __restrict__ Wv, const float* __restrict__ bv,
    float* pq, float* pk, float* pv){
  const float* W; const float* b; float* C;
  if (blockIdx.z == 0){ W = Wq; b = bq; C = pq; }
  else if (blockIdx.z == 1){ W = Wk; b = bk; C = pk; }
  else { W = Wv; b = bv; C = pv; }
  gemm_body<1,0>(x, W, b, C, BB*LL, DD, DD);
}

__global__ void __launch_bounds__(256) ffn_k(const float* __restrict__ A, const float* __restrict__ W,
                                             const float* __restrict__ bias, float* __restrict__ C,
                                             int M, int N, int K){
  gemm_body<0,1>(A, W, bias, C, M, N, K);
}

// ---------------- S = Q K^T per (b,h): 128x128 tile, 8x8 micro, transposed smem ----------------
__global__ void __launch_bounds__(256) sgemm128(){
  __shared__ __align__(16) float QsT[DIMH][132];
  __shared__ __align__(16) float KsT[DIMH][132];
  int bh = blockIdx.z;
  int q0 = blockIdx.y*128, k0 = blockIdx.x*128;
  const float* Q  = g_q + (size_t)bh*LL*DIMH;
  const float* Kp = g_k + (size_t)bh*LL*DIMH;
  int tid = threadIdx.x;
  const float4 z4 = make_float4(0.f,0.f,0.f,0.f);
  // 128 rows x 9 float4 = 1152 loads per tensor, transposed store
  for (int i = tid; i < 1152; i += 256){
    int r = i / 9, dv = i % 9;
    int gq = q0 + r, gk = k0 + r;
    float4 vq = (gq < LL) ? *(const float4*)(Q  + (size_t)gq*DIMH + 4*dv) : z4;
    float4 vk = (gk < LL) ? *(const float4*)(Kp + (size_t)gk*DIMH + 4*dv) : z4;
    QsT[4*dv+0][r] = vq.x; QsT[4*dv+1][r] = vq.y; QsT[4*dv+2][r] = vq.z; QsT[4*dv+3][r] = vq.w;
    KsT[4*dv+0][r] = vk.x; KsT[4*dv+1][r] = vk.y; KsT[4*dv+2][r] = vk.z; KsT[4*dv+3][r] = vk.w;
  }
  __syncthreads();
  int tx = tid & 15, ty = tid >> 4;
  float acc[8][8] = {};
#pragma unroll 4
  for (int d = 0; d < DIMH; d++){
    float4 a0 = *(const float4*)(&QsT[d][ty*8]);
    float4 a1 = *(const float4*)(&QsT[d][ty*8+4]);
    float4 b0 = *(const float4*)(&KsT[d][tx*8]);
    float4 b1 = *(const float4*)(&KsT[d][tx*8+4]);
    float a[8] = {a0.x,a0.y,a0.z,a0.w,a1.x,a1.y,a1.z,a1.w};
    float b[8] = {b0.x,b0.y,b0.z,b0.w,b1.x,b1.y,b1.z,b1.w};
#pragma unroll
    for (int i = 0; i < 8; i++)
#pragma unroll
      for (int j = 0; j < 8; j++) acc[i][j] += a[i]*b[j];
  }
  float* Sp = g_S + (size_t)bh*LL*LL;
  bool fullcol = (k0 + tx*8 + 7) < LL;
#pragma unroll
  for (int i = 0; i < 8; i++){
    int m = q0 + ty*8 + i;
    if (m >= LL) continue;
    float* dst = Sp + (size_t)m*LL + k0 + tx*8;
    if (fullcol){
      *(float4*)dst      = make_float4(acc[i][0],acc[i][1],acc[i][2],acc[i][3]);
      *(float4*)(dst+4)  = make_float4(acc[i][4],acc[i][5],acc[i][6],acc[i][7]);
    } else {
#pragma unroll
      for (int j = 0; j < 8; j++)
        if (k0 + tx*8 + j < LL) dst[j] = acc[i][j];
    }
  }
}

// ---------------- measure[l] = max_j S[l,idx[l,j]] - sum_j S[l,idx[l,j]] / L (warp/row) ----------------
__global__ void measure_k(const int* __restrict__ ik){
  int w = threadIdx.x >> 5, lane = threadIdx.x & 31;
  int l = blockIdx.x*8 + w, bh = blockIdx.y;
  if (l >= LL) return;
  const float* Srow = g_S + ((size_t)bh*LL + l)*LL;
  const int* row = ik + l*KS_;
  float mx = -INFINITY, s = 0.f;
  for (int j = lane; j < KS_; j += 32){
    float vv = Srow[row[j]];
    mx = fmaxf(mx, vv); s += vv;
  }
  mx = warpRedMax(mx);
  s  = warpRedSum(s);
  if (lane == 0) g_meas[bh*LL + l] = mx - s * (1.0f/(float)LL);
}

// ---------------- top-NQ per (b,h): bitonic sort 1024, 512 threads ----------------
__global__ void topk_k(){
  __shared__ float key[1024];
  __shared__ int   kid[1024];
  int bh = blockIdx.x, tid = threadIdx.x;
  for (int i = tid; i < 1024; i += 512){
    key[i] = (i < LL) ? -g_meas[bh*LL + i] : INFINITY;  // ascending of -measure
    kid[i] = i;
  }
  __syncthreads();
  for (int k = 2; k <= 1024; k <<= 1){
    for (int j = k >> 1; j > 0; j >>= 1){
      for (int i = tid; i < 1024; i += 512){
        int ixj = i ^ j;
        if (ixj > i){
          bool up = ((i & k) == 0);
          float a = key[i], b = key[ixj];
          int ia = kid[i], ib = kid[ixj];
          bool gt = (a > b) || (a == b && ia > ib);
          if (gt == up){
            key[i] = b; key[ixj] = a;
            kid[i] = ib; kid[ixj] = ia;
          }
        }
      }
      __syncthreads();
    }
  }
  for (int i = tid; i < NQ_; i += 512) g_idxq[bh*NQ_ + i] = kid[i];
}

// ---------------- per-selected-query softmax stats ----------------
__global__ void msum_k(){
  int tid = threadIdx.x;
  int w = tid >> 5, lane = tid & 31;
  int q = blockIdx.x*8 + w;
  int bh = blockIdx.y;
  if (q >= NQ_) return;
  const float sc = 1.0f/6.0f;
  int lq = g_idxq[bh*NQ_ + q];
  const float* row = g_S + ((size_t)bh*LL + lq)*LL;
  float mx = -INFINITY;
  for (int i = lane; i < LL; i += 32) mx = fmaxf(mx, row[i]);
  mx = warpRedMax(mx);
  float m = mx * sc;
  float s = 0.f;
  for (int i = lane; i < LL; i += 32) s += __expf(row[i]*sc - m);
  s = warpRedSum(s);
  if (lane == 0){ g_m[bh*NQ_ + q] = m; g_inv[bh*NQ_ + q] = 1.0f/s; }
}

// ---------------- fused softmax+PV, k-split partials ----------------
__global__ void __launch_bounds__(256) spv_k(){
  __shared__ float Ps[64][65];
  __shared__ float Vs[64][37];
  __shared__ float mS[64], invS[64];
  __shared__ int   lqS[64];
  int tid = threadIdx.x;
  int q0 = blockIdx.x*64;
  int ksb = blockIdx.y;
  int bh = blockIdx.z;
  int kstart = ksb*(LL/KSPLIT), kend = kstart + (LL/KSPLIT);
  const float sc = 1.0f/6.0f;
  if (tid < 64){
    int gq = q0 + tid;
    if (gq < NQ_){
      lqS[tid] = g_idxq[bh*NQ_ + gq];
      mS[tid]  = g_m[bh*NQ_ + gq];
      invS[tid]= g_inv[bh*NQ_ + gq];
    } else { lqS[tid]=0; mS[tid]=0.f; invS[tid]=0.f; }
  }
  __syncthreads();
  const float* Vp = g_v + (size_t)bh*LL*DIMH;
  const float* Sbh = g_S + (size_t)bh*LL*LL;
  int r = tid >> 2, cg = tid & 3;
  float acc[9] = {};
  for (int k0 = kstart; k0 < kend; k0 += 64){
    for (int i = tid; i < 64*DIMH; i += 256){
      int rr = i / DIMH, d = i % DIMH;
      int kr = k0 + rr;
      Vs[rr][d] = (kr < kend) ? Vp[(size_t)kr*DIMH + d] : 0.f;
    }
    for (int i = tid; i < 4096; i += 256){
      int qq = i >> 6, kk = i & 63;
      int kr = k0 + kk;
      float val = 0.f;
      if (q0 + qq < NQ_ && kr < kend)
        val = __expf(Sbh[(size_t)lqS[qq]*LL + kr]*sc - mS[qq]) * invS[qq];
      Ps[qq][kk] = val;
    }
    __syncthreads();
#pragma unroll 4
    for (int kk = 0; kk < 64; kk++){
      float p = Ps[r][kk];
#pragma unroll
      for (int c = 0; c < 9; c++) acc[c] += p * Vs[kk][cg*9 + c];
    }
    __syncthreads();
  }
  if (q0 + r < NQ_){
    float* dst = g_opart + (((size_t)ksb*BHN + bh)*NQ_ + q0 + r)*DIMH + cg*9;
#pragma unroll
    for (int c = 0; c < 9; c++) dst[c] = acc[c];
  }
}

// ---------------- vmean ----------------
__global__ void vmean_k(){
  __shared__ float sm[32];
  int d = blockIdx.x, bh = blockIdx.y, t = threadIdx.x;
  float s = 0.f;
  for (int l = t; l < LL; l += 256) s += g_v[((size_t)bh*LL + l)*DIMH + d];
  s = blockRedSum(s, sm, 8);
  if (t == 0) g_vmean[bh*DIMH + d] = s * (1.0f/(float)LL);
}

// ---------------- fill attn with broadcast vmean ----------------
__global__ void fill_k(){
  int idx = blockIdx.x*256 + threadIdx.x;
  if (idx >= BB*LL*DD) return;
  int c = idx % DD;
  int bl = idx / DD;
  int b_ = bl / LL;
  int h = c / DIMH, d = c % DIMH;
  g_attn[idx] = g_vmean[(b_*HH + h)*DIMH + d];
}

// ---------------- scatter active-query outputs (sums KSPLIT partials) ----------------
__global__ void scatter_k(){
  int qi = blockIdx.x, bh = blockIdx.y, t = threadIdx.x;
  if (t >= DIMH) return;
  int lstar = g_idxq[bh*NQ_ + qi];
  int b_ = bh / HH, h = bh % HH;
  float s = 0.f;
#pragma unroll
  for (int ks = 0; ks < KSPLIT; ks++)
    s += g_opart[(((size_t)ks*BHN + bh)*NQ_ + qi)*DIMH + t];
  g_attn[((size_t)b_*LL + lstar)*DD + h*DIMH + t] = s;
}

// ---------------- LayerNorm(A + B) ----------------
__global__ void ln_kernel(const float* __restrict__ A, const float* __restrict__ Bv,
                          const float* __restrict__ gamma, const float* __restrict__ beta,
                          float* __restrict__ out){
  __shared__ float sm[32];
  int row = blockIdx.x, t = threadIdx.x;  // 288 threads = 9 warps
  float s = A[(size_t)row*DD + t] + Bv[(size_t)row*DD + t];
  float mu = blockRedSum(s, sm, 9) * (1.0f/(float)DD);
  float d = s - mu;
  float var = blockRedSum(d*d, sm, 9) * (1.0f/(float)DD);
  out[(size_t)row*DD + t] = d * rsqrtf(var + 1e-5f) * gamma[t] + beta[t];
}

// ---------------- launch ----------------
extern "C" void kernel_launch(void* const* d_in, const int* in_sizes, int n_in,
                              void* d_out, int out_size){
  const float* x  = (const float*)d_in[0];
  const int*   ik = (const int*)  d_in[1];
  const float* Wq = (const float*)d_in[2];  const float* bq = (const float*)d_in[3];
  const float* Wk = (const float*)d_in[4];  const float* bk = (const float*)d_in[5];
  const float* Wv = (const float*)d_in[6];  const float* bv = (const float*)d_in[7];
  const float* W1 = (const float*)d_in[8];  const float* b1 = (const float*)d_in[9];
  const float* W2 = (const float*)d_in[10]; const float* b2 = (const float*)d_in[11];
  const float* g1 = (const float*)d_in[12]; const float* be1 = (const float*)d_in[13];
  const float* g2 = (const float*)d_in[14]; const float* be2 = (const float*)d_in[15];
  float* out = (float*)d_out;

  float *pq, *pk, *pv, *ph1, *pf1, *pf2, *pattn;
  cudaGetSymbolAddress((void**)&pq,   g_q);
  cudaGetSymbolAddress((void**)&pk,   g_k);
  cudaGetSymbolAddress((void**)&pv,   g_v);
  cudaGetSymbolAddress((void**)&ph1,  g_h1);
  cudaGetSymbolAddress((void**)&pf1,  g_f1);
  cudaGetSymbolAddress((void**)&pf2,  g_f2);
  cudaGetSymbolAddress((void**)&pattn, g_attn);

  const int M = BB*LL;  // 2000
  qkv_k<<<dim3(3, (M + 95)/96, 3), 256>>>(x, Wq, bq, Wk, bk, Wv, bv, pq, pk, pv);

  sgemm128<<<dim3(8, 8, BHN), 256>>>();
  measure_k<<<dim3((LL + 7)/8, BHN), 256>>>(ik);
  topk_k<<<BHN, 512>>>();
  msum_k<<<dim3((NQ_ + 7)/8, BHN), 256>>>();
  spv_k<<<dim3((NQ_ + 63)/64, KSPLIT, BHN), 256>>>();
  vmean_k<<<dim3(DIMH, BHN), 256>>>();
  fill_k<<<(BB*LL*DD + 255)/256, 256>>>();
  scatter_k<<<dim3(NQ_, BHN), 64>>>();

  ln_kernel<<<M, DD>>>(x, pattn, g1, be1, ph1);

  ffn_k<<<dim3((DFF_ + 95)/96, (M + 95)/96), 256>>>(ph1, W1, b1, pf1, M, DFF_, DD);
  ffn_k<<<dim3((DD   + 95)/96, (M + 95)/96), 256>>>(pf1, W2, b2, pf2, M, DD, DFF_);

  ln_kernel<<<M, DD>>>(pf2, ph1, g2, be2, out);
}

// round 5
// speedup vs baseline: 2.3493x; 1.0837x over previous
#include <cuda_runtime.h>
#include <math.h>

#define BB 2
#define LL 1000
#define DD 288
#define HH 8
#define DIMH 36
#define DFF_ 576
#define KS_ 250
#define NQ_ 250
#define BHN 16   // BB*HH
#define KSPLIT 4
#define FSPLIT 3   // ffn2 k-split

// ---------------- scratch (device globals; no allocs allowed) ----------------
__device__ __align__(16) float g_q[BHN*LL*DIMH];
__device__ __align__(16) float g_k[BHN*LL*DIMH];
__device__ __align__(16) float g_v[BHN*LL*DIMH];
__device__ __align__(16) float g_S[(size_t)BHN*LL*LL];      // 64 MB
__device__ float g_meas[BHN*LL];
__device__ int   g_idxq[BHN*NQ_];
__device__ float g_m[BHN*NQ_];
__device__ float g_inv[BHN*NQ_];
__device__ float g_opart[(size_t)KSPLIT*BHN*NQ_*DIMH];
__device__ float g_vmean[BHN*DIMH];
__device__ __align__(16) float g_attn[BB*LL*DD];
__device__ __align__(16) float g_h1[BB*LL*DD];
__device__ __align__(16) float g_f1[BB*LL*DFF_];
__device__ __align__(16) float g_f2[(size_t)FSPLIT*BB*LL*DD];

// ---------------- reduction helpers ----------------
__device__ __forceinline__ float warpRedSum(float v){
#pragma unroll
  for (int o=16;o;o>>=1) v += __shfl_xor_sync(0xffffffffu, v, o);
  return v;
}
__device__ __forceinline__ float warpRedMax(float v){
#pragma unroll
  for (int o=16;o;o>>=1) v = fmaxf(v, __shfl_xor_sync(0xffffffffu, v, o));
  return v;
}
__device__ float blockRedSum(float v, float* sm, int nwarp){
  int w = threadIdx.x >> 5, lane = threadIdx.x & 31;
  v = warpRedSum(v);
  if (lane == 0) sm[w] = v;
  __syncthreads();
  float r;
  if (w == 0){
    r = (lane < nwarp) ? sm[lane] : 0.f;
    r = warpRedSum(r);
    if (lane == 0) sm[0] = r;
  }
  __syncthreads();
  r = sm[0];
  __syncthreads();
  return r;
}

// ============ dense GEMM: 128x96 tile, 8x6 micro (rows ty+16*i) ============
// C = act(A[:, kStart:kStart+kLen] @ W[:, kStart:+kLen]^T + bias)
// A: [M, lda], W: [N, lda]. kLen % 32 == 0, N % 96 == 0.
// MODE 0: C[m*N+n] (+Cofs). MODE 1: scatter q/k/v layout.
template<int MODE, int GELU, int BIAS>
__device__ __forceinline__ void gemm_body(const float* __restrict__ A, const float* __restrict__ W,
                                          const float* __restrict__ bias, float* __restrict__ C,
                                          int M, int N, int lda, int kStart, int kLen){
  __shared__ __align__(16) float As[128][36];   // [m][kk] 32 used
  __shared__ float Bs[32][97];                  // [kk][n]
  int tid = threadIdx.x;
  int m0 = blockIdx.y * 128, n0 = blockIdx.x * 96;
  int tx = tid & 15, ty = tid >> 4;
  float acc[8][6] = {};
  float4 ra[4], rb[3];
  const float4 z4 = make_float4(0.f,0.f,0.f,0.f);

#pragma unroll
  for (int it = 0; it < 4; it++){
    int i = tid + it*256;
    int m = i >> 3, kv = i & 7;
    int gm = m0 + m;
    ra[it] = (gm < M) ? *(const float4*)(A + (size_t)gm*lda + kStart + 4*kv) : z4;
  }
#pragma unroll
  for (int it = 0; it < 3; it++){
    int i = tid + it*256;
    int n = i >> 3, kv = i & 7;
    rb[it] = *(const float4*)(W + (size_t)(n0 + n)*lda + kStart + 4*kv);
  }
#pragma unroll
  for (int it = 0; it < 4; it++){
    int i = tid + it*256;
    int m = i >> 3, kv = i & 7;
    *(float4*)(&As[m][4*kv]) = ra[it];
  }
#pragma unroll
  for (int it = 0; it < 3; it++){
    int i = tid + it*256;
    int n = i >> 3, kv = i & 7;
    Bs[4*kv+0][n] = rb[it].x; Bs[4*kv+1][n] = rb[it].y;
    Bs[4*kv+2][n] = rb[it].z; Bs[4*kv+3][n] = rb[it].w;
  }
  __syncthreads();

  for (int k0 = 0; k0 < kLen; k0 += 32){
    bool more = (k0 + 32) < kLen;
    if (more){
      int kg = kStart + k0 + 32;
#pragma unroll
      for (int it = 0; it < 4; it++){
        int i = tid + it*256;
        int m = i >> 3, kv = i & 7;
        int gm = m0 + m;
        ra[it] = (gm < M) ? *(const float4*)(A + (size_t)gm*lda + kg + 4*kv) : z4;
      }
#pragma unroll
      for (int it = 0; it < 3; it++){
        int i = tid + it*256;
        int n = i >> 3, kv = i & 7;
        rb[it] = *(const float4*)(W + (size_t)(n0 + n)*lda + kg + 4*kv);
      }
    }
#pragma unroll 4
    for (int kk = 0; kk < 32; kk++){
      float a[8], b[6];
#pragma unroll
      for (int i = 0; i < 8; i++) a[i] = As[ty + 16*i][kk];
#pragma unroll
      for (int j = 0; j < 6; j++) b[j] = Bs[kk][tx*6+j];
#pragma unroll
      for (int i = 0; i < 8; i++)
#pragma unroll
        for (int j = 0; j < 6; j++) acc[i][j] += a[i]*b[j];
    }
    __syncthreads();
    if (more){
#pragma unroll
      for (int it = 0; it < 4; it++){
        int i = tid + it*256;
        int m = i >> 3, kv = i & 7;
        *(float4*)(&As[m][4*kv]) = ra[it];
      }
#pragma unroll
      for (int it = 0; it < 3; it++){
        int i = tid + it*256;
        int n = i >> 3, kv = i & 7;
        Bs[4*kv+0][n] = rb[it].x; Bs[4*kv+1][n] = rb[it].y;
        Bs[4*kv+2][n] = rb[it].z; Bs[4*kv+3][n] = rb[it].w;
      }
      __syncthreads();
    }
  }
#pragma unroll
  for (int i = 0; i < 8; i++){
    int m = m0 + ty + 16*i;
    if (m >= M) continue;
#pragma unroll
    for (int j = 0; j < 6; j++){
      int n = n0 + tx*6 + j;
      float vv = acc[i][j];
      if (BIAS) vv += bias[n];
      if (GELU) vv = 0.5f*vv*(1.0f + erff(vv*0.70710678118654752f));
      if (MODE == 0){
        C[(size_t)m*N + n] = vv;
      } else {
        int b_ = m / LL, l = m % LL;
        int h = n / DIMH, d = n % DIMH;
        C[(((size_t)b_*HH + h)*LL + l)*DIMH + d] = vv;
      }
    }
  }
}

__global__ void __launch_bounds__(256) qkv_k(const float* __restrict__ x,
    const float* __restrict__ Wq, const float* __restrict__ bq,
    const float* __restrict__ Wk, const float* __restrict__ bk,
    const float* __restrict__ Wv, const float* __restrict__ bv,
    float* pq, float* pk, float* pv){
  const float* W; const float* b; float* C;
  if (blockIdx.z == 0){ W = Wq; b = bq; C = pq; }
  else if (blockIdx.z == 1){ W = Wk; b = bk; C = pk; }
  else { W = Wv; b = bv; C = pv; }
  gemm_body<1,0,1>(x, W, b, C, BB*LL, DD, DD, 0, DD);
}

__global__ void __launch_bounds__(256) ffn1_k(const float* __restrict__ A, const float* __restrict__ W,
                                              const float* __restrict__ bias, float* __restrict__ C){
  gemm_body<0,1,1>(A, W, bias, C, BB*LL, DFF_, DD, 0, DD);
}

// ffn2 partial: K split into FSPLIT chunks; raw partial (no bias/gelu)
__global__ void __launch_bounds__(256) ffn2_k(const float* __restrict__ A, const float* __restrict__ W,
                                              float* __restrict__ C){
  int ks = blockIdx.z;
  const int kLen = DFF_/FSPLIT;   // 192
  gemm_body<0,0,0>(A, W, nullptr, C + (size_t)ks*BB*LL*DD, BB*LL, DD, DFF_, ks*kLen, kLen);
}

// ---------------- S = Q K^T per (b,h): 128x128 tile, 8x8 micro ----------------
__global__ void __launch_bounds__(256) sgemm128(){
  __shared__ __align__(16) float QsT[DIMH][132];
  __shared__ __align__(16) float KsT[DIMH][132];
  int bh = blockIdx.z;
  int q0 = blockIdx.y*128, k0 = blockIdx.x*128;
  const float* Q  = g_q + (size_t)bh*LL*DIMH;
  const float* Kp = g_k + (size_t)bh*LL*DIMH;
  int tid = threadIdx.x;
  const float4 z4 = make_float4(0.f,0.f,0.f,0.f);
  for (int i = tid; i < 1152; i += 256){
    int r = i / 9, dv = i % 9;
    int gq = q0 + r, gk = k0 + r;
    float4 vq = (gq < LL) ? *(const float4*)(Q  + (size_t)gq*DIMH + 4*dv) : z4;
    float4 vk = (gk < LL) ? *(const float4*)(Kp + (size_t)gk*DIMH + 4*dv) : z4;
    QsT[4*dv+0][r] = vq.x; QsT[4*dv+1][r] = vq.y; QsT[4*dv+2][r] = vq.z; QsT[4*dv+3][r] = vq.w;
    KsT[4*dv+0][r] = vk.x; KsT[4*dv+1][r] = vk.y; KsT[4*dv+2][r] = vk.z; KsT[4*dv+3][r] = vk.w;
  }
  __syncthreads();
  int tx = tid & 15, ty = tid >> 4;
  float acc[8][8] = {};
#pragma unroll 4
  for (int d = 0; d < DIMH; d++){
    float4 a0 = *(const float4*)(&QsT[d][ty*8]);
    float4 a1 = *(const float4*)(&QsT[d][ty*8+4]);
    float4 b0 = *(const float4*)(&KsT[d][tx*8]);
    float4 b1 = *(const float4*)(&KsT[d][tx*8+4]);
    float a[8] = {a0.x,a0.y,a0.z,a0.w,a1.x,a1.y,a1.z,a1.w};
    float b[8] = {b0.x,b0.y,b0.z,b0.w,b1.x,b1.y,b1.z,b1.w};
#pragma unroll
    for (int i = 0; i < 8; i++)
#pragma unroll
      for (int j = 0; j < 8; j++) acc[i][j] += a[i]*b[j];
  }
  float* Sp = g_S + (size_t)bh*LL*LL;
  bool fullcol = (k0 + tx*8 + 7) < LL;
#pragma unroll
  for (int i = 0; i < 8; i++){
    int m = q0 + ty*8 + i;
    if (m >= LL) continue;
    float* dst = Sp + (size_t)m*LL + k0 + tx*8;
    if (fullcol){
      *(float4*)dst      = make_float4(acc[i][0],acc[i][1],acc[i][2],acc[i][3]);
      *(float4*)(dst+4)  = make_float4(acc[i][4],acc[i][5],acc[i][6],acc[i][7]);
    } else {
#pragma unroll
      for (int j = 0; j < 8; j++)
        if (k0 + tx*8 + j < LL) dst[j] = acc[i][j];
    }
  }
}

// ---------------- measure (warp/row) ----------------
__global__ void measure_k(const int* __restrict__ ik){
  int w = threadIdx.x >> 5, lane = threadIdx.x & 31;
  int l = blockIdx.x*8 + w, bh = blockIdx.y;
  if (l >= LL) return;
  const float* Srow = g_S + ((size_t)bh*LL + l)*LL;
  const int* row = ik + l*KS_;
  float mx = -INFINITY, s = 0.f;
  for (int j = lane; j < KS_; j += 32){
    float vv = Srow[row[j]];
    mx = fmaxf(mx, vv); s += vv;
  }
  mx = warpRedMax(mx);
  s  = warpRedSum(s);
  if (lane == 0) g_meas[bh*LL + l] = mx - s * (1.0f/(float)LL);
}

// ---------------- top-NQ per (b,h): radix select (top 250 of 1000) ----------------
__global__ void __launch_bounds__(256) topk_k(){
  __shared__ unsigned key[LL];
  __shared__ int hist[256];
  __shared__ int suf[256];
  __shared__ int s_digit, s_r, s_cnt;
  int bh = blockIdx.x, tid = threadIdx.x;
  for (int i = tid; i < LL; i += 256){
    unsigned u = __float_as_uint(g_meas[bh*LL + i]);
    key[i] = (u & 0x80000000u) ? ~u : (u | 0x80000000u);  // ascending-sortable
  }
  __syncthreads();
  unsigned prefix = 0;
  int r = NQ_;
  for (int pass = 0; pass < 4; pass++){
    int shift = 24 - pass*8;
    hist[tid] = 0;
    __syncthreads();
    for (int i = tid; i < LL; i += 256){
      unsigned u = key[i];
      bool act = (pass == 0) || ((u >> (shift + 8)) == prefix);
      if (act) atomicAdd(&hist[(u >> shift) & 255], 1);
    }
    __syncthreads();
    suf[tid] = hist[tid];
    __syncthreads();
    for (int off = 1; off < 256; off <<= 1){
      int t = (tid + off < 256) ? suf[tid + off] : 0;
      __syncthreads();
      suf[tid] += t;
      __syncthreads();
    }
    int incl = suf[tid];
    int grt = incl - hist[tid];
    if (grt < r && r <= incl){ s_digit = tid; s_r = r - grt; }
    __syncthreads();
    prefix = (prefix << 8) | (unsigned)s_digit;
    r = s_r;
    __syncthreads();
  }
  unsigned T = prefix;
  if (tid == 0) s_cnt = 0;
  __syncthreads();
  for (int i = tid; i < LL; i += 256){
    if (key[i] > T){
      int pos = atomicAdd(&s_cnt, 1);
      g_idxq[bh*NQ_ + pos] = i;
    }
  }
  __syncthreads();
  int base = s_cnt;   // = NQ_ - r
  for (int i = tid; i < LL; i += 256){
    if (key[i] == T){
      int cb = 0;
      for (int j = 0; j < i; j++) cb += (key[j] == T);
      if (cb < r) g_idxq[bh*NQ_ + base + cb] = i;   // lowest indices first (jax tie rule)
    }
  }
}

// ---------------- per-selected-query softmax stats ----------------
__global__ void msum_k(){
  int tid = threadIdx.x;
  int w = tid >> 5, lane = tid & 31;
  int q = blockIdx.x*8 + w;
  int bh = blockIdx.y;
  if (q >= NQ_) return;
  const float sc = 1.0f/6.0f;
  int lq = g_idxq[bh*NQ_ + q];
  const float* row = g_S + ((size_t)bh*LL + lq)*LL;
  float mx = -INFINITY;
  for (int i = lane; i < LL; i += 32) mx = fmaxf(mx, row[i]);
  mx = warpRedMax(mx);
  float m = mx * sc;
  float s = 0.f;
  for (int i = lane; i < LL; i += 32) s += __expf(row[i]*sc - m);
  s = warpRedSum(s);
  if (lane == 0){ g_m[bh*NQ_ + q] = m; g_inv[bh*NQ_ + q] = 1.0f/s; }
}

// ---------------- fused softmax+PV, k-split partials ----------------
__global__ void __launch_bounds__(256) spv_k(){
  __shared__ float Ps[64][65];
  __shared__ float Vs[64][37];
  __shared__ float mS[64], invS[64];
  __shared__ int   lqS[64];
  int tid = threadIdx.x;
  int q0 = blockIdx.x*64;
  int ksb = blockIdx.y;
  int bh = blockIdx.z;
  int kstart = ksb*(LL/KSPLIT), kend = kstart + (LL/KSPLIT);
  const float sc = 1.0f/6.0f;
  if (tid < 64){
    int gq = q0 + tid;
    if (gq < NQ_){
      lqS[tid] = g_idxq[bh*NQ_ + gq];
      mS[tid]  = g_m[bh*NQ_ + gq];
      invS[tid]= g_inv[bh*NQ_ + gq];
    } else { lqS[tid]=0; mS[tid]=0.f; invS[tid]=0.f; }
  }
  __syncthreads();
  const float* Vp = g_v + (size_t)bh*LL*DIMH;
  const float* Sbh = g_S + (size_t)bh*LL*LL;
  int r = tid >> 2, cg = tid & 3;
  float acc[9] = {};
  for (int k0 = kstart; k0 < kend; k0 += 64){
    for (int i = tid; i < 64*DIMH; i += 256){
      int rr = i / DIMH, d = i % DIMH;
      int kr = k0 + rr;
      Vs[rr][d] = (kr < kend) ? Vp[(size_t)kr*DIMH + d] : 0.f;
    }
    for (int i = tid; i < 4096; i += 256){
      int qq = i >> 6, kk = i & 63;
      int kr = k0 + kk;
      float val = 0.f;
      if (q0 + qq < NQ_ && kr < kend)
        val = __expf(Sbh[(size_t)lqS[qq]*LL + kr]*sc - mS[qq]) * invS[qq];
      Ps[qq][kk] = val;
    }
    __syncthreads();
#pragma unroll 4
    for (int kk = 0; kk < 64; kk++){
      float p = Ps[r][kk];
#pragma unroll
      for (int c = 0; c < 9; c++) acc[c] += p * Vs[kk][cg*9 + c];
    }
    __syncthreads();
  }
  if (q0 + r < NQ_){
    float* dst = g_opart + (((size_t)ksb*BHN + bh)*NQ_ + q0 + r)*DIMH + cg*9;
#pragma unroll
    for (int c = 0; c < 9; c++) dst[c] = acc[c];
  }
}

// ---------------- vmean ----------------
__global__ void vmean_k(){
  __shared__ float sm[32];
  int d = blockIdx.x, bh = blockIdx.y, t = threadIdx.x;
  float s = 0.f;
  for (int l = t; l < LL; l += 256) s += g_v[((size_t)bh*LL + l)*DIMH + d];
  s = blockRedSum(s, sm, 8);
  if (t == 0) g_vmean[bh*DIMH + d] = s * (1.0f/(float)LL);
}

// ---------------- fill attn with broadcast vmean ----------------
__global__ void fill_k(){
  int idx = blockIdx.x*256 + threadIdx.x;
  if (idx >= BB*LL*DD) return;
  int c = idx % DD;
  int bl = idx / DD;
  int b_ = bl / LL;
  int h = c / DIMH, d = c % DIMH;
  g_attn[idx] = g_vmean[(b_*HH + h)*DIMH + d];
}

// ---------------- scatter active-query outputs (sums KSPLIT partials) ----------------
__global__ void scatter_k(){
  int qi = blockIdx.x, bh = blockIdx.y, t = threadIdx.x;
  if (t >= DIMH) return;
  int lstar = g_idxq[bh*NQ_ + qi];
  int b_ = bh / HH, h = bh % HH;
  float s = 0.f;
#pragma unroll
  for (int ks = 0; ks < KSPLIT; ks++)
    s += g_opart[(((size_t)ks*BHN + bh)*NQ_ + qi)*DIMH + t];
  g_attn[((size_t)b_*LL + lstar)*DD + h*DIMH + t] = s;
}

// ---------------- LayerNorm(A + B) ----------------
__global__ void ln_kernel(const float* __restrict__ A, const float* __restrict__ Bv,
                          const float* __restrict__ gamma, const float* __restrict__ beta,
                          float* __restrict__ out){
  __shared__ float sm[32];
  int row = blockIdx.x, t = threadIdx.x;
  float s = A[(size_t)row*DD + t] + Bv[(size_t)row*DD + t];
  float mu = blockRedSum(s, sm, 9) * (1.0f/(float)DD);
  float d = s - mu;
  float var = blockRedSum(d*d, sm, 9) * (1.0f/(float)DD);
  out[(size_t)row*DD + t] = d * rsqrtf(var + 1e-5f) * gamma[t] + beta[t];
}

// ---------------- LN2: sum ffn2 partials + bias -> GELU -> +h1 -> LN ----------------
__global__ void ln2_kernel(const float* __restrict__ f2p, const float* __restrict__ b2,
                           const float* __restrict__ h1,
                           const float* __restrict__ gamma, const float* __restrict__ beta,
                           float* __restrict__ out){
  __shared__ float sm[32];
  int row = blockIdx.x, t = threadIdx.x;
  size_t o = (size_t)row*DD + t;
  const size_t stride = (size_t)BB*LL*DD;
  float v = f2p[o] + f2p[stride + o] + f2p[2*stride + o] + b2[t];
  v = 0.5f*v*(1.0f + erff(v*0.70710678118654752f));
  float s = v + h1[o];
  float mu = blockRedSum(s, sm, 9) * (1.0f/(float)DD);
  float d = s - mu;
  float var = blockRedSum(d*d, sm, 9) * (1.0f/(float)DD);
  out[o] = d * rsqrtf(var + 1e-5f) * gamma[t] + beta[t];
}

// ---------------- launch ----------------
extern "C" void kernel_launch(void* const* d_in, const int* in_sizes, int n_in,
                              void* d_out, int out_size){
  const float* x  = (const float*)d_in[0];
  const int*   ik = (const int*)  d_in[1];
  const float* Wq = (const float*)d_in[2];  const float* bq = (const float*)d_in[3];
  const float* Wk = (const float*)d_in[4];  const float* bk = (const float*)d_in[5];
  const float* Wv = (const float*)d_in[6];  const float* bv = (const float*)d_in[7];
  const float* W1 = (const float*)d_in[8];  const float* b1 = (const float*)d_in[9];
  const float* W2 = (const float*)d_in[10]; const float* b2 = (const float*)d_in[11];
  const float* g1 = (const float*)d_in[12]; const float* be1 = (const float*)d_in[13];
  const float* g2 = (const float*)d_in[14]; const float* be2 = (const float*)d_in[15];
  float* out = (float*)d_out;

  float *pq, *pk, *pv, *ph1, *pf1, *pf2, *pattn;
  cudaGetSymbolAddress((void**)&pq,   g_q);
  cudaGetSymbolAddress((void**)&pk,   g_k);
  cudaGetSymbolAddress((void**)&pv,   g_v);
  cudaGetSymbolAddress((void**)&ph1,  g_h1);
  cudaGetSymbolAddress((void**)&pf1,  g_f1);
  cudaGetSymbolAddress((void**)&pf2,  g_f2);
  cudaGetSymbolAddress((void**)&pattn, g_attn);

  const int M = BB*LL;  // 2000
  qkv_k<<<dim3(DD/96, (M + 127)/128, 3), 256>>>(x, Wq, bq, Wk, bk, Wv, bv, pq, pk, pv);

  sgemm128<<<dim3(8, 8, BHN), 256>>>();
  measure_k<<<dim3((LL + 7)/8, BHN), 256>>>(ik);
  topk_k<<<BHN, 256>>>();
  msum_k<<<dim3((NQ_ + 7)/8, BHN), 256>>>();
  spv_k<<<dim3((NQ_ + 63)/64, KSPLIT, BHN), 256>>>();
  vmean_k<<<dim3(DIMH, BHN), 256>>>();
  fill_k<<<(BB*LL*DD + 255)/256, 256>>>();
  scatter_k<<<dim3(NQ_, BHN), 64>>>();

  ln_kernel<<<M, DD>>>(x, pattn, g1, be1, ph1);

  ffn1_k<<<dim3(DFF_/96, (M + 127)/128), 256>>>(ph1, W1, b1, pf1);
  ffn2_k<<<dim3(DD/96, (M + 127)/128, FSPLIT), 256>>>(pf1, W2, pf2);

  ln2_kernel<<<M, DD>>>(pf2, b2, ph1, g2, be2, out);
}

// round 6
// speedup vs baseline: 2.5310x; 1.0773x over previous
#include <cuda_runtime.h>
#include <math.h>

#define BB 2
#define LL 1000
#define DD 288
#define HH 8
#define DIMH 36
#define DFF_ 576
#define KS_ 250
#define NQ_ 250
#define BHN 16   // BB*HH
#define KSPLIT 4
#define FSPLIT 3   // ffn2 k-split

// ---------------- scratch (device globals; no allocs allowed) ----------------
__device__ __align__(16) float g_q[BHN*LL*DIMH];
__device__ __align__(16) float g_k[BHN*LL*DIMH];
__device__ __align__(16) float g_v[BHN*LL*DIMH];
__device__ __align__(16) float g_S[(size_t)BHN*LL*LL];      // 64 MB
__device__ float g_meas[BHN*LL];
__device__ int   g_idxq[BHN*NQ_];
__device__ int   g_inv[BHN*LL];
__device__ float g_m[BHN*NQ_];
__device__ float g_invs[BHN*NQ_];
__device__ float g_opart[(size_t)KSPLIT*BHN*NQ_*DIMH];
__device__ float g_vmean[BHN*DIMH];
__device__ __align__(16) float g_h1[BB*LL*DD];
__device__ __align__(16) float g_f1[BB*LL*DFF_];
__device__ __align__(16) float g_f2[(size_t)FSPLIT*BB*LL*DD];

// ---------------- reduction helpers ----------------
__device__ __forceinline__ float warpRedSum(float v){
#pragma unroll
  for (int o=16;o;o>>=1) v += __shfl_xor_sync(0xffffffffu, v, o);
  return v;
}
__device__ __forceinline__ float warpRedMax(float v){
#pragma unroll
  for (int o=16;o;o>>=1) v = fmaxf(v, __shfl_xor_sync(0xffffffffu, v, o));
  return v;
}
__device__ float blockRedSum(float v, float* sm, int nwarp){
  int w = threadIdx.x >> 5, lane = threadIdx.x & 31;
  v = warpRedSum(v);
  if (lane == 0) sm[w] = v;
  __syncthreads();
  float r;
  if (w == 0){
    r = (lane < nwarp) ? sm[lane] : 0.f;
    r = warpRedSum(r);
    if (lane == 0) sm[0] = r;
  }
  __syncthreads();
  r = sm[0];
  __syncthreads();
  return r;
}

// ============ dense GEMM: MTx96 tile (MT in {64,128}), 8x6 micro, 2*MT threads ============
// C = act(A[:, kStart:kStart+kLen] @ W[:, kStart:+kLen]^T + bias)
// A: [M, lda], W: [N, lda]. kLen % 32 == 0, N % 96 == 0.
template<int MT, int MODE, int GELU, int BIAS>
__device__ __forceinline__ void gemm_body(const float* __restrict__ A, const float* __restrict__ W,
                                          const float* __restrict__ bias, float* __restrict__ C,
                                          int M, int N, int lda, int kStart, int kLen){
  const int NT = 2*MT;          // threads
  const int RS = MT/8;          // row stride in micro loop
  const int NB = 384/MT;        // B float4 loads per thread
  __shared__ __align__(16) float As[MT][36];   // [m][kk] 32 used
  __shared__ float Bs[32][97];                 // [kk][n]
  int tid = threadIdx.x;
  int m0 = blockIdx.y * MT, n0 = blockIdx.x * 96;
  int tx = tid & 15, ty = tid >> 4;
  float acc[8][6] = {};
  float4 ra[4], rb[NB];
  const float4 z4 = make_float4(0.f,0.f,0.f,0.f);

#pragma unroll
  for (int it = 0; it < 4; it++){
    int i = tid + it*NT;
    int m = i >> 3, kv = i & 7;
    int gm = m0 + m;
    ra[it] = (gm < M) ? *(const float4*)(A + (size_t)gm*lda + kStart + 4*kv) : z4;
  }
#pragma unroll
  for (int it = 0; it < NB; it++){
    int i = tid + it*NT;
    int n = i >> 3, kv = i & 7;
    rb[it] = *(const float4*)(W + (size_t)(n0 + n)*lda + kStart + 4*kv);
  }
#pragma unroll
  for (int it = 0; it < 4; it++){
    int i = tid + it*NT;
    int m = i >> 3, kv = i & 7;
    *(float4*)(&As[m][4*kv]) = ra[it];
  }
#pragma unroll
  for (int it = 0; it < NB; it++){
    int i = tid + it*NT;
    int n = i >> 3, kv = i & 7;
    Bs[4*kv+0][n] = rb[it].x; Bs[4*kv+1][n] = rb[it].y;
    Bs[4*kv+2][n] = rb[it].z; Bs[4*kv+3][n] = rb[it].w;
  }
  __syncthreads();

  for (int k0 = 0; k0 < kLen; k0 += 32){
    bool more = (k0 + 32) < kLen;
    if (more){
      int kg = kStart + k0 + 32;
#pragma unroll
      for (int it = 0; it < 4; it++){
        int i = tid + it*NT;
        int m = i >> 3, kv = i & 7;
        int gm = m0 + m;
        ra[it] = (gm < M) ? *(const float4*)(A + (size_t)gm*lda + kg + 4*kv) : z4;
      }
#pragma unroll
      for (int it = 0; it < NB; it++){
        int i = tid + it*NT;
        int n = i >> 3, kv = i & 7;
        rb[it] = *(const float4*)(W + (size_t)(n0 + n)*lda + kg + 4*kv);
      }
    }
#pragma unroll 4
    for (int kk = 0; kk < 32; kk++){
      float a[8], b[6];
#pragma unroll
      for (int i = 0; i < 8; i++) a[i] = As[ty + RS*i][kk];
#pragma unroll
      for (int j = 0; j < 6; j++) b[j] = Bs[kk][tx*6+j];
#pragma unroll
      for (int i = 0; i < 8; i++)
#pragma unroll
        for (int j = 0; j < 6; j++) acc[i][j] += a[i]*b[j];
    }
    __syncthreads();
    if (more){
#pragma unroll
      for (int it = 0; it < 4; it++){
        int i = tid + it*NT;
        int m = i >> 3, kv = i & 7;
        *(float4*)(&As[m][4*kv]) = ra[it];
      }
#pragma unroll
      for (int it = 0; it < NB; it++){
        int i = tid + it*NT;
        int n = i >> 3, kv = i & 7;
        Bs[4*kv+0][n] = rb[it].x; Bs[4*kv+1][n] = rb[it].y;
        Bs[4*kv+2][n] = rb[it].z; Bs[4*kv+3][n] = rb[it].w;
      }
      __syncthreads();
    }
  }
#pragma unroll
  for (int i = 0; i < 8; i++){
    int m = m0 + ty + RS*i;
    if (m >= M) continue;
#pragma unroll
    for (int j = 0; j < 6; j++){
      int n = n0 + tx*6 + j;
      float vv = acc[i][j];
      if (BIAS) vv += bias[n];
      if (GELU) vv = 0.5f*vv*(1.0f + erff(vv*0.70710678118654752f));
      if (MODE == 0){
        C[(size_t)m*N + n] = vv;
      } else {
        int b_ = m / LL, l = m % LL;
        int h = n / DIMH, d = n % DIMH;
        C[(((size_t)b_*HH + h)*LL + l)*DIMH + d] = vv;
      }
    }
  }
}

__global__ void __launch_bounds__(256) qkv_k(const float* __restrict__ x,
    const float* __restrict__ Wq, const float* __restrict__ bq,
    const float* __restrict__ Wk, const float* __restrict__ bk,
    const float* __restrict__ Wv, const float* __restrict__ bv,
    float* pq, float* pk, float* pv){
  const float* W; const float* b; float* C;
  if (blockIdx.z == 0){ W = Wq; b = bq; C = pq; }
  else if (blockIdx.z == 1){ W = Wk; b = bk; C = pk; }
  else { W = Wv; b = bv; C = pv; }
  gemm_body<128,1,0,1>(x, W, b, C, BB*LL, DD, DD, 0, DD);
}

__global__ void __launch_bounds__(128) ffn1_k(const float* __restrict__ A, const float* __restrict__ W,
                                              const float* __restrict__ bias, float* __restrict__ C){
  gemm_body<64,0,1,1>(A, W, bias, C, BB*LL, DFF_, DD, 0, DD);
}

// ffn2 partial: K split into FSPLIT chunks; raw partial (no bias/gelu)
__global__ void __launch_bounds__(256) ffn2_k(const float* __restrict__ A, const float* __restrict__ W,
                                              float* __restrict__ C){
  int ks = blockIdx.z;
  const int kLen = DFF_/FSPLIT;   // 192
  gemm_body<128,0,0,0>(A, W, nullptr, C + (size_t)ks*BB*LL*DD, BB*LL, DD, DFF_, ks*kLen, kLen);
}

// ---------------- S = Q K^T per (b,h): 128x128 tile, 8x8 micro ----------------
__global__ void __launch_bounds__(256) sgemm128(){
  __shared__ __align__(16) float QsT[DIMH][132];
  __shared__ __align__(16) float KsT[DIMH][132];
  int bh = blockIdx.z;
  int q0 = blockIdx.y*128, k0 = blockIdx.x*128;
  const float* Q  = g_q + (size_t)bh*LL*DIMH;
  const float* Kp = g_k + (size_t)bh*LL*DIMH;
  int tid = threadIdx.x;
  const float4 z4 = make_float4(0.f,0.f,0.f,0.f);
  for (int i = tid; i < 1152; i += 256){
    int r = i / 9, dv = i % 9;
    int gq = q0 + r, gk = k0 + r;
    float4 vq = (gq < LL) ? *(const float4*)(Q  + (size_t)gq*DIMH + 4*dv) : z4;
    float4 vk = (gk < LL) ? *(const float4*)(Kp + (size_t)gk*DIMH + 4*dv) : z4;
    QsT[4*dv+0][r] = vq.x; QsT[4*dv+1][r] = vq.y; QsT[4*dv+2][r] = vq.z; QsT[4*dv+3][r] = vq.w;
    KsT[4*dv+0][r] = vk.x; KsT[4*dv+1][r] = vk.y; KsT[4*dv+2][r] = vk.z; KsT[4*dv+3][r] = vk.w;
  }
  __syncthreads();
  int tx = tid & 15, ty = tid >> 4;
  float acc[8][8] = {};
#pragma unroll 4
  for (int d = 0; d < DIMH; d++){
    float4 a0 = *(const float4*)(&QsT[d][ty*8]);
    float4 a1 = *(const float4*)(&QsT[d][ty*8+4]);
    float4 b0 = *(const float4*)(&KsT[d][tx*8]);
    float4 b1 = *(const float4*)(&KsT[d][tx*8+4]);
    float a[8] = {a0.x,a0.y,a0.z,a0.w,a1.x,a1.y,a1.z,a1.w};
    float b[8] = {b0.x,b0.y,b0.z,b0.w,b1.x,b1.y,b1.z,b1.w};
#pragma unroll
    for (int i = 0; i < 8; i++)
#pragma unroll
      for (int j = 0; j < 8; j++) acc[i][j] += a[i]*b[j];
  }
  float* Sp = g_S + (size_t)bh*LL*LL;
  bool fullcol = (k0 + tx*8 + 7) < LL;
#pragma unroll
  for (int i = 0; i < 8; i++){
    int m = q0 + ty*8 + i;
    if (m >= LL) continue;
    float* dst = Sp + (size_t)m*LL + k0 + tx*8;
    if (fullcol){
      *(float4*)dst      = make_float4(acc[i][0],acc[i][1],acc[i][2],acc[i][3]);
      *(float4*)(dst+4)  = make_float4(acc[i][4],acc[i][5],acc[i][6],acc[i][7]);
    } else {
#pragma unroll
      for (int j = 0; j < 8; j++)
        if (k0 + tx*8 + j < LL) dst[j] = acc[i][j];
    }
  }
}

// ---------------- measure (warp/row) ----------------
__global__ void measure_k(const int* __restrict__ ik){
  int w = threadIdx.x >> 5, lane = threadIdx.x & 31;
  int l = blockIdx.x*8 + w, bh = blockIdx.y;
  if (l >= LL) return;
  const float* Srow = g_S + ((size_t)bh*LL + l)*LL;
  const int* row = ik + l*KS_;
  float mx = -INFINITY, s = 0.f;
  for (int j = lane; j < KS_; j += 32){
    float vv = Srow[row[j]];
    mx = fmaxf(mx, vv); s += vv;
  }
  mx = warpRedMax(mx);
  s  = warpRedSum(s);
  if (lane == 0) g_meas[bh*LL + l] = mx - s * (1.0f/(float)LL);
}

// ---------------- top-NQ per (b,h): register radix select, scan-based gather ----------------
// Each thread owns 4 contiguous keys (1000 = 250*4). Writes g_idxq set and g_inv map.
__global__ void __launch_bounds__(256) topk_k(){
  __shared__ int hist[256];
  __shared__ int warpbase[9];
  __shared__ int s_digit, s_r;
  int bh = blockIdx.x, tid = threadIdx.x;
  bool real = tid < 250;
  unsigned kv[4] = {0,0,0,0};
  if (real){
#pragma unroll
    for (int j = 0; j < 4; j++){
      unsigned u = __float_as_uint(g_meas[bh*LL + 4*tid + j]);
      kv[j] = (u & 0x80000000u) ? ~u : (u | 0x80000000u);  // order-preserving map
    }
  }
  hist[tid] = 0;
  __syncthreads();
  unsigned prefix = 0; int r = NQ_;
#pragma unroll
  for (int pass = 0; pass < 4; pass++){
    int shift = 24 - pass*8;
    if (real){
#pragma unroll
      for (int j = 0; j < 4; j++){
        unsigned u = kv[j];
        if (pass == 0 || (u >> (shift + 8)) == prefix)
          atomicAdd(&hist[(u >> shift) & 255], 1);
      }
    }
    __syncthreads();
    if (tid < 32){
      int b[8], suf[8]; int acc = 0;
#pragma unroll
      for (int j = 7; j >= 0; j--){ b[j] = hist[tid*8 + j]; acc += b[j]; suf[j] = acc; }
      int inc = acc;
#pragma unroll
      for (int off = 1; off < 32; off <<= 1){
        int t = __shfl_down_sync(0xffffffffu, inc, off);
        if (tid + off < 32) inc += t;
      }
      int hiex = inc - acc;   // keys in higher lanes' bins
#pragma unroll
      for (int j = 0; j < 8; j++){
        int ge = suf[j] + hiex;      // count >= this digit
        int gt = ge - b[j];          // count > this digit
        if (gt < r && r <= ge){ s_digit = tid*8 + j; s_r = r - gt; }
      }
    }
    __syncthreads();
    prefix = (prefix << 8) | (unsigned)s_digit;
    r = s_r;
    hist[tid] = 0;
    __syncthreads();
  }
  unsigned T = prefix;
  // fused (greater,equal) block scan; index order preserved
  int cg = 0, ce = 0; int locg[4], loce[4];
  if (real){
#pragma unroll
    for (int j = 0; j < 4; j++){
      locg[j] = cg; loce[j] = ce;
      cg += (kv[j] > T); ce += (kv[j] == T);
    }
  }
  int pack = (cg << 16) | ce;
  int lane = tid & 31, w = tid >> 5;
  int sc = pack;
#pragma unroll
  for (int off = 1; off < 32; off <<= 1){
    int t = __shfl_up_sync(0xffffffffu, sc, off);
    if (lane >= off) sc += t;
  }
  if (lane == 31) warpbase[w+1] = sc;
  if (tid == 0) warpbase[0] = 0;
  __syncthreads();
  if (tid == 0){ for (int i = 1; i < 8; i++) warpbase[i+1] += warpbase[i]; }
  __syncthreads();
  int excl = sc - pack + warpbase[w];
  int eg = excl >> 16, ee = excl & 0xffff;
  if (real){
#pragma unroll
    for (int j = 0; j < 4; j++){
      int i = 4*tid + j;
      int pos = -1;
      if (kv[j] > T) pos = eg + locg[j];
      else if (kv[j] == T){
        int rk = ee + loce[j];
        if (rk < r) pos = (NQ_ - r) + rk;   // lowest indices among ties (jax rule)
      }
      g_inv[bh*LL + i] = pos;
      if (pos >= 0) g_idxq[bh*NQ_ + pos] = i;
    }
  }
}

// ---------------- per-selected-query softmax stats ----------------
__global__ void msum_k(){
  int tid = threadIdx.x;
  int w = tid >> 5, lane = tid & 31;
  int q = blockIdx.x*8 + w;
  int bh = blockIdx.y;
  if (q >= NQ_) return;
  const float sc = 1.0f/6.0f;
  int lq = g_idxq[bh*NQ_ + q];
  const float* row = g_S + ((size_t)bh*LL + lq)*LL;
  float mx = -INFINITY;
  for (int i = lane; i < LL; i += 32) mx = fmaxf(mx, row[i]);
  mx = warpRedMax(mx);
  float m = mx * sc;
  float s = 0.f;
  for (int i = lane; i < LL; i += 32) s += __expf(row[i]*sc - m);
  s = warpRedSum(s);
  if (lane == 0){ g_m[bh*NQ_ + q] = m; g_invs[bh*NQ_ + q] = 1.0f/s; }
}

// ---------------- fused softmax+PV, k-split partials ----------------
__global__ void __launch_bounds__(256) spv_k(){
  __shared__ float Ps[64][65];
  __shared__ float Vs[64][37];
  __shared__ float mS[64], invS[64];
  __shared__ int   lqS[64];
  int tid = threadIdx.x;
  int q0 = blockIdx.x*64;
  int ksb = blockIdx.y;
  int bh = blockIdx.z;
  int kstart = ksb*(LL/KSPLIT), kend = kstart + (LL/KSPLIT);
  const float sc = 1.0f/6.0f;
  if (tid < 64){
    int gq = q0 + tid;
    if (gq < NQ_){
      lqS[tid] = g_idxq[bh*NQ_ + gq];
      mS[tid]  = g_m[bh*NQ_ + gq];
      invS[tid]= g_invs[bh*NQ_ + gq];
    } else { lqS[tid]=0; mS[tid]=0.f; invS[tid]=0.f; }
  }
  __syncthreads();
  const float* Vp = g_v + (size_t)bh*LL*DIMH;
  const float* Sbh = g_S + (size_t)bh*LL*LL;
  int r = tid >> 2, cg = tid & 3;
  float acc[9] = {};
  for (int k0 = kstart; k0 < kend; k0 += 64){
    for (int i = tid; i < 64*DIMH; i += 256){
      int rr = i / DIMH, d = i % DIMH;
      int kr = k0 + rr;
      Vs[rr][d] = (kr < kend) ? Vp[(size_t)kr*DIMH + d] : 0.f;
    }
    for (int i = tid; i < 4096; i += 256){
      int qq = i >> 6, kk = i & 63;
      int kr = k0 + kk;
      float val = 0.f;
      if (q0 + qq < NQ_ && kr < kend)
        val = __expf(Sbh[(size_t)lqS[qq]*LL + kr]*sc - mS[qq]) * invS[qq];
      Ps[qq][kk] = val;
    }
    __syncthreads();
#pragma unroll 4
    for (int kk = 0; kk < 64; kk++){
      float p = Ps[r][kk];
#pragma unroll
      for (int c = 0; c < 9; c++) acc[c] += p * Vs[kk][cg*9 + c];
    }
    __syncthreads();
  }
  if (q0 + r < NQ_){
    float* dst = g_opart + (((size_t)ksb*BHN + bh)*NQ_ + q0 + r)*DIMH + cg*9;
#pragma unroll
    for (int c = 0; c < 9; c++) dst[c] = acc[c];
  }
}

// ---------------- vmean ----------------
__global__ void vmean_k(){
  __shared__ float sm[32];
  int d = blockIdx.x, bh = blockIdx.y, t = threadIdx.x;
  float s = 0.f;
  for (int l = t; l < LL; l += 256) s += g_v[((size_t)bh*LL + l)*DIMH + d];
  s = blockRedSum(s, sm, 8);
  if (t == 0) g_vmean[bh*DIMH + d] = s * (1.0f/(float)LL);
}

// ---------------- LN1 fused: gather attn (opart partial-sum or vmean) + x, then LN ----------------
__global__ void ln1f_kernel(const float* __restrict__ x,
                            const float* __restrict__ gamma, const float* __restrict__ beta,
                            float* __restrict__ out){
  __shared__ float sm[32];
  int row = blockIdx.x, t = threadIdx.x;   // 288 threads
  int b_ = row / LL, l = row % LL;
  int h = t / DIMH, d = t % DIMH;
  int bh = b_*HH + h;
  int qi = g_inv[bh*LL + l];
  float attn;
  if (qi >= 0){
    attn = 0.f;
#pragma unroll
    for (int ks = 0; ks < KSPLIT; ks++)
      attn += g_opart[(((size_t)ks*BHN + bh)*NQ_ + qi)*DIMH + d];
  } else {
    attn = g_vmean[bh*DIMH + d];
  }
  float s = x[(size_t)row*DD + t] + attn;
  float mu = blockRedSum(s, sm, 9) * (1.0f/(float)DD);
  float dd = s - mu;
  float var = blockRedSum(dd*dd, sm, 9) * (1.0f/(float)DD);
  out[(size_t)row*DD + t] = dd * rsqrtf(var + 1e-5f) * gamma[t] + beta[t];
}

// ---------------- LN2: sum ffn2 partials + bias -> GELU -> +h1 -> LN ----------------
__global__ void ln2_kernel(const float* __restrict__ f2p, const float* __restrict__ b2,
                           const float* __restrict__ h1,
                           const float* __restrict__ gamma, const float* __restrict__ beta,
                           float* __restrict__ out){
  __shared__ float sm[32];
  int row = blockIdx.x, t = threadIdx.x;
  size_t o = (size_t)row*DD + t;
  const size_t stride = (size_t)BB*LL*DD;
  float v = f2p[o] + f2p[stride + o] + f2p[2*stride + o] + b2[t];
  v = 0.5f*v*(1.0f + erff(v*0.70710678118654752f));
  float s = v + h1[o];
  float mu = blockRedSum(s, sm, 9) * (1.0f/(float)DD);
  float d = s - mu;
  float var = blockRedSum(d*d, sm, 9) * (1.0f/(float)DD);
  out[o] = d * rsqrtf(var + 1e-5f) * gamma[t] + beta[t];
}

// ---------------- launch ----------------
extern "C" void kernel_launch(void* const* d_in, const int* in_sizes, int n_in,
                              void* d_out, int out_size){
  const float* x  = (const float*)d_in[0];
  const int*   ik = (const int*)  d_in[1];
  const float* Wq = (const float*)d_in[2];  const float* bq = (const float*)d_in[3];
  const float* Wk = (const float*)d_in[4];  const float* bk = (const float*)d_in[5];
  const float* Wv = (const float*)d_in[6];  const float* bv = (const float*)d_in[7];
  const float* W1 = (const float*)d_in[8];  const float* b1 = (const float*)d_in[9];
  const float* W2 = (const float*)d_in[10]; const float* b2 = (const float*)d_in[11];
  const float* g1 = (const float*)d_in[12]; const float* be1 = (const float*)d_in[13];
  const float* g2 = (const float*)d_in[14]; const float* be2 = (const float*)d_in[15];
  float* out = (float*)d_out;

  float *pq, *pk, *pv, *ph1, *pf1, *pf2;
  cudaGetSymbolAddress((void**)&pq,   g_q);
  cudaGetSymbolAddress((void**)&pk,   g_k);
  cudaGetSymbolAddress((void**)&pv,   g_v);
  cudaGetSymbolAddress((void**)&ph1,  g_h1);
  cudaGetSymbolAddress((void**)&pf1,  g_f1);
  cudaGetSymbolAddress((void**)&pf2,  g_f2);

  const int M = BB*LL;  // 2000
  qkv_k<<<dim3(DD/96, (M + 127)/128, 3), 256>>>(x, Wq, bq, Wk, bk, Wv, bv, pq, pk, pv);

  sgemm128<<<dim3(8, 8, BHN), 256>>>();
  measure_k<<<dim3((LL + 7)/8, BHN), 256>>>(ik);
  topk_k<<<BHN, 256>>>();
  msum_k<<<dim3((NQ_ + 7)/8, BHN), 256>>>();
  spv_k<<<dim3((NQ_ + 63)/64, KSPLIT, BHN), 256>>>();
  vmean_k<<<dim3(DIMH, BHN), 256>>>();

  ln1f_kernel<<<M, DD>>>(x, g1, be1, ph1);

  ffn1_k<<<dim3(DFF_/96, (M + 63)/64), 128>>>(ph1, W1, b1, pf1);
  ffn2_k<<<dim3(DD/96, (M + 127)/128, FSPLIT), 256>>>(pf1, W2, pf2);

  ln2_kernel<<<M, DD>>>(pf2, b2, ph1, g2, be2, out);
}